// round 12
// baseline (speedup 1.0000x reference)
#include <cuda_runtime.h>
#include <math.h>

#define BSZ 4
#define SEQ 1024
#define DMODEL 512
#define NH 8
#define DHD 64
#define INNER_DIM 1536
#define MTOT (BSZ*SEQ)   /* 4096 */

// ---------------- scratch (device globals; no runtime allocation) ----------------
__device__ float g_q   [MTOT*DMODEL];
__device__ float g_kv  [MTOT*2*DMODEL];
__device__ float g_o   [MTOT*DMODEL];
__device__ float g_att [MTOT*DMODEL];
__device__ float g_h   [MTOT*DMODEL];
__device__ float g_u1  [MTOT*INNER_DIM];
__device__ float g_gate[MTOT*INNER_DIM];
__device__ float g_ffn [MTOT*DMODEL];
__device__ float g_y   [MTOT*DMODEL];
__device__ float g_psum[BSZ*32*DMODEL];
__device__ float g_psq [BSZ*32*DMODEL];
__device__ float g_mean[BSZ*DMODEL];
__device__ float g_rstd[BSZ*DMODEL];
__device__ float g_sc  [(size_t)BSZ*NH*SEQ*SEQ];   /* 134MB score/coef matrix */
__device__ float g_sinv[BSZ*NH*SEQ];

// ---------------- helpers ----------------
__device__ __forceinline__ unsigned f2key(float f) {
    unsigned u = __float_as_uint(f);
    return (u & 0x80000000u) ? ~u : (u | 0x80000000u);
}
__device__ __forceinline__ float key2f(unsigned k) {
    unsigned u = (k & 0x80000000u) ? (k & 0x7fffffffu) : ~k;
    return __uint_as_float(u);
}
__device__ __forceinline__ unsigned warpMaxU(unsigned v) {
    #pragma unroll
    for (int o = 16; o; o >>= 1) v = umax(v, __shfl_xor_sync(0xffffffffu, v, o));
    return v;
}
__device__ __forceinline__ int warpMaxI(int v) {
    #pragma unroll
    for (int o = 16; o; o >>= 1) v = max(v, __shfl_xor_sync(0xffffffffu, v, o));
    return v;
}
__device__ __forceinline__ float warpSum(float v) {
    #pragma unroll
    for (int o = 16; o; o >>= 1) v += __shfl_xor_sync(0xffffffffu, v, o);
    return v;
}
__device__ __forceinline__ unsigned to_tf32(float x) {
    unsigned u;
    asm("cvt.rna.tf32.f32 %0, %1;" : "=r"(u) : "f"(x));
    return u;
}
__device__ __forceinline__ float4 to_tf32x4(float4 v) {
    float4 r;
    r.x = __uint_as_float(to_tf32(v.x));
    r.y = __uint_as_float(to_tf32(v.y));
    r.z = __uint_as_float(to_tf32(v.z));
    r.w = __uint_as_float(to_tf32(v.w));
    return r;
}
__device__ __forceinline__ void ldsm4(unsigned* r, unsigned saddr) {
    asm volatile("ldmatrix.sync.aligned.m8n8.x4.shared.b16 {%0,%1,%2,%3}, [%4];"
                 : "=r"(r[0]), "=r"(r[1]), "=r"(r[2]), "=r"(r[3]) : "r"(saddr));
}
__device__ __forceinline__ void mma_tf32(float* d, const unsigned* a, const unsigned* b) {
    asm volatile(
        "mma.sync.aligned.m16n8k8.row.col.f32.tf32.tf32.f32 "
        "{%0,%1,%2,%3}, {%4,%5,%6,%7}, {%8,%9}, {%0,%1,%2,%3};"
        : "+f"(d[0]), "+f"(d[1]), "+f"(d[2]), "+f"(d[3])
        : "r"(a[0]), "r"(a[1]), "r"(a[2]), "r"(a[3]), "r"(b[0]), "r"(b[1]));
}

// ---------------- TF32 tensor-core GEMM: C[M,N] = A[M,K] @ B[K,N] ----------------
// Block tile BMxBN=128, BK=32, 256 threads = 8 warps (2M x 4N), warp tile (BM/2)x32.
// Templated: BM in {64,128}; AUX selects silu(aux)*val epilogue (else +bias).
#define GBK 32
#define B_STRIDE 136             /* 128 + 8 pad */
#define B_BUF_F32 (GBK*B_STRIDE) /* 4352 */

template<int BM, bool AUX>
__global__ __launch_bounds__(256, 2) void tf32gemm_kernel(
    const float* __restrict__ A, const float* __restrict__ B,
    const float* __restrict__ bias, const float* __restrict__ aux,
    float* __restrict__ C, int M, int N, int K)
{
    constexpr int ABUF = BM * GBK;     // floats per A stage
    constexpr int MT   = BM / 32;      // m-tiles (of 16) per warp
    extern __shared__ float gsm[];
    float* AsF = gsm;                  // 2 * ABUF
    float* BsF = gsm + 2*ABUF;         // 2 * B_BUF_F32
    const unsigned asBase = (unsigned)__cvta_generic_to_shared(AsF);

    const int tid = threadIdx.x, lane = tid & 31, wid = tid >> 5;
    const int warpM = wid & 1, warpN = wid >> 1;
    const int bm = blockIdx.y * BM, bn = blockIdx.x * 128;

    const int mbase = warpM*(BM/2) + ((lane>>3)&1)*8 + (lane&7);
    const int jhi   = lane >> 4;
    const int xorv  = lane & 7;
    const int kb    = lane & 3;
    const int nbase = warpN*32 + (lane>>2);

    float acc[MT][4][4];
    #pragma unroll
    for (int mt = 0; mt < MT; ++mt)
        #pragma unroll
        for (int nt = 0; nt < 4; ++nt)
            #pragma unroll
            for (int i = 0; i < 4; ++i) acc[mt][nt][i] = 0.0f;

    const int am = tid >> 3, ak4 = tid & 7;      // A staging: rows am + 32p
    const int bk = tid >> 5, bn4 = tid & 31;     // B staging: rows bk + 8p

    float4 regA[MT], regB[4];
    #pragma unroll
    for (int p = 0; p < MT; ++p)
        regA[p] = *(const float4*)(A + (size_t)(bm + am + p*32)*K + ak4*4);
    #pragma unroll
    for (int p = 0; p < 4; ++p)
        regB[p] = *(const float4*)(B + (size_t)(bk + p*8)*N + bn + bn4*4);
    #pragma unroll
    for (int p = 0; p < MT; ++p) {
        int m = am + p*32;
        int unit = m*8 + (ak4 ^ (m & 7));
        *(float4*)(AsF + unit*4) = to_tf32x4(regA[p]);
    }
    #pragma unroll
    for (int p = 0; p < 4; ++p)
        *(float4*)(BsF + (bk + p*8)*B_STRIDE + bn4*4) = to_tf32x4(regB[p]);
    __syncthreads();

    const int nIter = K / GBK;
    int buf = 0;
    for (int kt = 0; kt < nIter; ++kt) {
        bool more = (kt + 1 < nIter);
        if (more) {
            int k0 = (kt+1)*GBK;
            #pragma unroll
            for (int p = 0; p < MT; ++p)
                regA[p] = *(const float4*)(A + (size_t)(bm + am + p*32)*K + k0 + ak4*4);
            #pragma unroll
            for (int p = 0; p < 4; ++p)
                regB[p] = *(const float4*)(B + (size_t)(k0 + bk + p*8)*N + bn + bn4*4);
        }

        const unsigned aBufBase = asBase + buf*(ABUF*4);
        const float* bb = BsF + buf*B_BUF_F32;
        #pragma unroll
        for (int ks = 0; ks < 4; ++ks) {
            unsigned af[MT][4];
            #pragma unroll
            for (int mt = 0; mt < MT; ++mt) {
                int m = mbase + mt*16;
                int unit = m*8 + ((ks*2 + jhi) ^ xorv);
                ldsm4(af[mt], aBufBase + unit*16);
            }
            unsigned bf[4][2];
            #pragma unroll
            for (int nt = 0; nt < 4; ++nt) {
                bf[nt][0] = __float_as_uint(bb[(ks*8 + kb    )*B_STRIDE + nbase + nt*8]);
                bf[nt][1] = __float_as_uint(bb[(ks*8 + kb + 4)*B_STRIDE + nbase + nt*8]);
            }
            #pragma unroll
            for (int mt = 0; mt < MT; ++mt)
                #pragma unroll
                for (int nt = 0; nt < 4; ++nt)
                    mma_tf32(acc[mt][nt], af[mt], bf[nt]);
        }

        if (more) {
            int nb = buf ^ 1;
            float* AsW = AsF + nb*ABUF;
            float* BsW = BsF + nb*B_BUF_F32;
            #pragma unroll
            for (int p = 0; p < MT; ++p) {
                int m = am + p*32;
                int unit = m*8 + (ak4 ^ (m & 7));
                *(float4*)(AsW + unit*4) = to_tf32x4(regA[p]);
            }
            #pragma unroll
            for (int p = 0; p < 4; ++p)
                *(float4*)(BsW + (bk + p*8)*B_STRIDE + bn4*4) = to_tf32x4(regB[p]);
        }
        __syncthreads();
        buf ^= 1;
    }

    const int gr = lane >> 2, gc = (lane & 3) * 2;
    #pragma unroll
    for (int nt = 0; nt < 4; ++nt) {
        int col = bn + warpN*32 + nt*8 + gc;
        float b0v = (!AUX && bias) ? bias[col]   : 0.0f;
        float b1v = (!AUX && bias) ? bias[col+1] : 0.0f;
        #pragma unroll
        for (int mt = 0; mt < MT; ++mt) {
            int row = bm + warpM*(BM/2) + mt*16 + gr;
            float c0 = acc[mt][nt][0] + b0v, c1 = acc[mt][nt][1] + b1v;
            float c2 = acc[mt][nt][2] + b0v, c3 = acc[mt][nt][3] + b1v;
            if (AUX) {
                float2 a0 = *(const float2*)(aux + (size_t)row*N + col);
                float2 a1 = *(const float2*)(aux + (size_t)(row+8)*N + col);
                c0 *= a0.x / (1.f + __expf(-a0.x));
                c1 *= a0.y / (1.f + __expf(-a0.y));
                c2 *= a1.x / (1.f + __expf(-a1.x));
                c3 *= a1.y / (1.f + __expf(-a1.y));
            }
            *(float2*)(C + (size_t)row*N + col)     = make_float2(c0, c1);
            *(float2*)(C + (size_t)(row+8)*N + col) = make_float2(c2, c3);
        }
    }
}

// ---------------- attention stage 1: scores S[bh,i,t] = (q_i . k_t)/8 ----------------
// grid (SEQ/128 t-tiles, SEQ/128 i-tiles, BSZ*NH), 256 threads
#define SST 68
__global__ __launch_bounds__(256) void scores_kernel(
    const float* __restrict__ qb, const float* __restrict__ kvb, float* __restrict__ scb)
{
    extern __shared__ float smem[];
    float* sQ = smem;            // 128*SST
    float* sK = smem + 128*SST;  // 128*SST
    const int tid = threadIdx.x, lane = tid & 31, wid = tid >> 5;
    const int bh = blockIdx.z, b = bh >> 3, h = bh & 7;
    const int i0 = blockIdx.y * 128, t0 = blockIdx.x * 128;

    #pragma unroll
    for (int p = 0; p < 8; ++p) {
        int idx = tid + p*256;
        int row = idx >> 4, c4 = (idx & 15) << 2;
        *(float4*)(sQ + row*SST + c4) =
            to_tf32x4(*(const float4*)(qb + (size_t)(b*SEQ + i0 + row)*DMODEL + h*DHD + c4));
    }
    #pragma unroll
    for (int p = 0; p < 8; ++p) {
        int idx = tid + p*256;
        int row = idx >> 4, c4 = (idx & 15) << 2;
        *(float4*)(sK + row*SST + c4) =
            to_tf32x4(*(const float4*)(kvb + (size_t)(b*SEQ + t0 + row)*(2*DMODEL) + h*DHD + c4));
    }
    __syncthreads();

    const int warpM = wid & 1, warpN = wid >> 1;   // 2 x 4 warps -> warp tile 64i x 32t
    const int g = lane >> 2, fb = lane & 3;

    float acc[4][4][4];
    #pragma unroll
    for (int mt = 0; mt < 4; ++mt)
        #pragma unroll
        for (int nt = 0; nt < 4; ++nt)
            #pragma unroll
            for (int i = 0; i < 4; ++i) acc[mt][nt][i] = 0.0f;

    #pragma unroll
    for (int ks = 0; ks < 8; ++ks) {
        unsigned af[4][4], bf[4][2];
        #pragma unroll
        for (int mt = 0; mt < 4; ++mt) {
            const float* ap = sQ + (warpM*64 + mt*16 + g)*SST + ks*8 + fb;
            af[mt][0] = __float_as_uint(ap[0]);
            af[mt][1] = __float_as_uint(ap[8*SST]);
            af[mt][2] = __float_as_uint(ap[4]);
            af[mt][3] = __float_as_uint(ap[8*SST + 4]);
        }
        #pragma unroll
        for (int nt = 0; nt < 4; ++nt) {
            const float* bp = sK + (warpN*32 + nt*8 + g)*SST + ks*8 + fb;
            bf[nt][0] = __float_as_uint(bp[0]);
            bf[nt][1] = __float_as_uint(bp[4]);
        }
        #pragma unroll
        for (int mt = 0; mt < 4; ++mt)
            #pragma unroll
            for (int nt = 0; nt < 4; ++nt)
                mma_tf32(acc[mt][nt], af[mt], bf[nt]);
    }

    #pragma unroll
    for (int mt = 0; mt < 4; ++mt) {
        int iLo = i0 + warpM*64 + mt*16 + g;
        #pragma unroll
        for (int nt = 0; nt < 4; ++nt) {
            int t = t0 + warpN*32 + nt*8 + 2*fb;
            *(float2*)(scb + ((size_t)bh*SEQ + iLo)*SEQ + t) =
                make_float2(acc[mt][nt][0]*0.125f, acc[mt][nt][1]*0.125f);
            *(float2*)(scb + ((size_t)bh*SEQ + iLo + 8)*SEQ + t) =
                make_float2(acc[mt][nt][2]*0.125f, acc[mt][nt][3]*0.125f);
        }
    }
}

// ---------------- attention stage 2: per-row softmax + top-512 + coef rewrite ----------------
// 1 warp per row, 8 rows per block; keys in smem; pass-0 histogram fused into load loop
__global__ __launch_bounds__(256, 4) void select_kernel(
    float* __restrict__ scb, float* __restrict__ sinvb)
{
    __shared__ unsigned skeys[8][1024];
    __shared__ int hist[8*256];
    const int tid = threadIdx.x, lane = tid & 31, wid = tid >> 5;
    const int r = blockIdx.x*8 + wid;
    float* row = scb + (size_t)r*SEQ;
    unsigned* keys = skeys[wid];
    int* wh = hist + wid*256;

    // zero pass-0 histogram, then load scores -> keys while histogramming top byte
    #pragma unroll
    for (int i = 0; i < 8; ++i) wh[lane*8 + i] = 0;
    __syncwarp();
    unsigned mk = 0;
    #pragma unroll
    for (int j = 0; j < 32; ++j) {
        unsigned key = f2key(row[j*32 + lane]);
        keys[j*32 + lane] = key;
        mk = umax(mk, key);
        unsigned digit = key >> 24;
        unsigned grp = __match_any_sync(0xffffffffu, digit);
        if (((int)__ffs(grp) - 1) == lane) wh[digit] += __popc(grp);
    }
    mk = warpMaxU(mk);
    const float m = key2f(mk);
    float z1 = 0.f;
    #pragma unroll
    for (int j = 0; j < 32; ++j)
        z1 += __expf(key2f(keys[j*32 + lane]) - m);
    z1 = warpSum(z1);
    const float invZ1 = 1.0f / z1;

    // MSB radix select (4x8-bit); pass 0 histogram already built; alive-mask pruning
    const unsigned MASKS[4]  = {0u, 0xff000000u, 0xffff0000u, 0xffffff00u};
    const int      SHIFTS[4] = {24, 16, 8, 0};
    unsigned alive = 0xffffffffu;
    unsigned prefix = 0;
    int k = SEQ/2;
    #pragma unroll
    for (int pi = 0; pi < 4; ++pi) {
        const int shift = SHIFTS[pi];
        if (pi > 0) {
            const unsigned maskHi = MASKS[pi];
            #pragma unroll
            for (int i = 0; i < 8; ++i) wh[lane*8 + i] = 0;
            __syncwarp();
            unsigned msk = alive;
            int mx = warpMaxI(__popc(msk));
            for (int it = 0; it < mx; ++it) {
                unsigned digit = 0xffffffffu;
                if (msk) {
                    int j = __ffs(msk) - 1;
                    msk &= msk - 1;
                    unsigned key = keys[j*32 + lane];
                    if (((key ^ prefix) & maskHi) == 0u) digit = (key >> shift) & 255u;
                    else alive &= ~(1u << j);
                }
                unsigned grp = __match_any_sync(0xffffffffu, digit);
                if (digit != 0xffffffffu && ((int)__ffs(grp) - 1) == lane)
                    wh[digit] += __popc(grp);
            }
        }
        __syncwarp();
        int h8[8]; int vv = 0;
        #pragma unroll
        for (int i = 0; i < 8; ++i) { h8[i] = wh[lane*8 + i]; vv += h8[i]; }
        int inc = vv;
        #pragma unroll
        for (int o = 1; o < 32; o <<= 1) {
            int tt = __shfl_down_sync(0xffffffffu, inc, o);
            if (lane + o < 32) inc += tt;
        }
        int above = inc - vv;
        int sel = -1, newk = 0;
        if (above < k && inc >= k) {
            int csum = above;
            #pragma unroll
            for (int j = 7; j >= 0; --j) {
                int hc = h8[j];
                if (csum + hc >= k) { sel = lane*8 + j; newk = k - csum; break; }
                csum += hc;
            }
        }
        unsigned bal = __ballot_sync(0xffffffffu, sel >= 0);
        int srcl = __ffs(bal) - 1;
        sel = __shfl_sync(0xffffffffu, sel, srcl);
        k   = __shfl_sync(0xffffffffu, newk, srcl);
        prefix |= ((unsigned)sel) << shift;
        __syncwarp();
    }
    const unsigned tauKey = prefix;
    const int needEq = k;

    // collect equal-to-tau indices
    if (lane == 0) wh[0] = 0;
    __syncwarp();
    unsigned eqmask = 0;
    #pragma unroll
    for (int j = 0; j < 32; ++j) {
        if (keys[j*32 + lane] == tauKey) {
            int p = atomicAdd(&wh[0], 1);
            if (p < 255) wh[1 + p] = j*32 + lane;
            eqmask |= 1u << j;
        }
    }
    __syncwarp();
    int neq = wh[0];
    int listN = neq < 255 ? neq : 255;
    float ctau = __uint_as_float(to_tf32(__expf(__expf(key2f(tauKey) - m) * invZ1)));

    // coefficient write + Z2
    float z2 = 0.f;
    #pragma unroll
    for (int j = 0; j < 32; ++j) {
        unsigned key = keys[j*32 + lane];
        float coef = 1.0f;
        if (key > tauKey)
            coef = __uint_as_float(to_tf32(__expf(__expf(key2f(key) - m) * invZ1)));
        row[j*32 + lane] = coef;
        z2 += coef;
    }
    z2 = warpSum(z2);

    // resolve ties (jax rule: earliest t kept)
    if (eqmask) {
        unsigned em = eqmask;
        while (em) {
            int j = __ffs(em) - 1;
            em &= em - 1;
            int t = j*32 + lane;
            int rank = 0;
            for (int q = 0; q < listN; ++q) rank += (wh[1 + q] < t);
            if (rank < needEq) row[t] = ctau;
        }
    }
    int keptEq = needEq < neq ? needEq : neq;
    z2 += (ctau - 1.0f) * (float)keptEq;
    if (lane == 0) sinvb[r] = 1.0f / z2;
}

// ---------------- attention stage 3: O[bh] = diag(1/Z2) * W @ V ----------------
// grid (SEQ/64 i-tiles, BSZ*NH), 256 threads; tile 64i x 64dh, k-chunks of 64, reg prefetch
#define AWST 68
#define AVST 72
__global__ __launch_bounds__(256) void av_kernel(
    const float* __restrict__ scb, const float* __restrict__ kvb,
    const float* __restrict__ sinvb, float* __restrict__ ob)
{
    __shared__ float sW[64*AWST];
    __shared__ float sV[64*AVST];
    const int tid = threadIdx.x, lane = tid & 31, wid = tid >> 5;
    const int bh = blockIdx.y, b = bh >> 3, h = bh & 7;
    const int i0 = blockIdx.x * 64;
    const int warpM = wid & 1, warpN = wid >> 1;   // warp tile 32i x 16dh
    const int g = lane >> 2, fb = lane & 3;

    const int ldRow = tid >> 4, ldC4 = (tid & 15) << 2;   // 16 rows per pass, 4 passes

    float acc[2][2][4];
    #pragma unroll
    for (int mt = 0; mt < 2; ++mt)
        #pragma unroll
        for (int nt = 0; nt < 2; ++nt)
            #pragma unroll
            for (int i = 0; i < 4; ++i) acc[mt][nt][i] = 0.0f;

    float4 pW[4], pV[4];
    #pragma unroll
    for (int p = 0; p < 4; ++p) {
        int rowi = ldRow + p*16;
        pW[p] = *(const float4*)(scb + ((size_t)bh*SEQ + i0 + rowi)*SEQ + ldC4);
        pV[p] = to_tf32x4(*(const float4*)(kvb + (size_t)(b*SEQ + rowi)*(2*DMODEL) + DMODEL + h*DHD + ldC4));
    }

    for (int c = 0; c < SEQ/64; ++c) {
        #pragma unroll
        for (int p = 0; p < 4; ++p) {
            int rowi = ldRow + p*16;
            *(float4*)(sW + rowi*AWST + ldC4) = pW[p];
            *(float4*)(sV + rowi*AVST + ldC4) = pV[p];
        }
        __syncthreads();
        if (c + 1 < SEQ/64) {
            #pragma unroll
            for (int p = 0; p < 4; ++p) {
                int rowi = ldRow + p*16;
                pW[p] = *(const float4*)(scb + ((size_t)bh*SEQ + i0 + rowi)*SEQ + (c+1)*64 + ldC4);
                pV[p] = to_tf32x4(*(const float4*)(kvb + (size_t)(b*SEQ + (c+1)*64 + rowi)*(2*DMODEL) + DMODEL + h*DHD + ldC4));
            }
        }

        #pragma unroll
        for (int ks = 0; ks < 8; ++ks) {
            unsigned af[2][4], bf[2][2];
            #pragma unroll
            for (int mt = 0; mt < 2; ++mt) {
                const float* ap = sW + (warpM*32 + mt*16 + g)*AWST + ks*8 + fb;
                af[mt][0] = __float_as_uint(ap[0]);
                af[mt][1] = __float_as_uint(ap[8*AWST]);
                af[mt][2] = __float_as_uint(ap[4]);
                af[mt][3] = __float_as_uint(ap[8*AWST + 4]);
            }
            #pragma unroll
            for (int nt = 0; nt < 2; ++nt) {
                const float* bp = sV + (ks*8 + fb)*AVST + warpN*16 + nt*8 + g;
                bf[nt][0] = __float_as_uint(bp[0]);
                bf[nt][1] = __float_as_uint(bp[4*AVST]);
            }
            #pragma unroll
            for (int mt = 0; mt < 2; ++mt)
                #pragma unroll
                for (int nt = 0; nt < 2; ++nt)
                    mma_tf32(acc[mt][nt], af[mt], bf[nt]);
        }
        __syncthreads();
    }

    #pragma unroll
    for (int mt = 0; mt < 2; ++mt) {
        int iLo = i0 + warpM*32 + mt*16 + g;
        int iHi = iLo + 8;
        float zLo = sinvb[bh*SEQ + iLo];
        float zHi = sinvb[bh*SEQ + iHi];
        #pragma unroll
        for (int nt = 0; nt < 2; ++nt) {
            int col = h*DHD + warpN*16 + nt*8 + 2*fb;
            *(float2*)(ob + (size_t)(b*SEQ + iLo)*DMODEL + col) =
                make_float2(acc[mt][nt][0]*zLo, acc[mt][nt][1]*zLo);
            *(float2*)(ob + (size_t)(b*SEQ + iHi)*DMODEL + col) =
                make_float2(acc[mt][nt][2]*zHi, acc[mt][nt][3]*zHi);
        }
    }
}

// ---------------- residual + RMSNorm (per row of 512) ----------------
__global__ __launch_bounds__(128) void rms_add_kernel(
    const float* __restrict__ x, const float* __restrict__ a,
    const float* __restrict__ w, float* __restrict__ out)
{
    __shared__ float red[4];
    int row = blockIdx.x;
    int t = threadIdx.x;
    const float4* x4 = (const float4*)(x + (size_t)row*DMODEL);
    const float4* a4 = (const float4*)(a + (size_t)row*DMODEL);
    float4 xv = x4[t], av = a4[t];
    float4 s = make_float4(xv.x+av.x, xv.y+av.y, xv.z+av.z, xv.w+av.w);
    float ss = s.x*s.x + s.y*s.y + s.z*s.z + s.w*s.w;
    ss = warpSum(ss);
    if ((t & 31) == 0) red[t >> 5] = ss;
    __syncthreads();
    float tot = red[0] + red[1] + red[2] + red[3];
    float inv = rsqrtf(tot * (1.0f/DMODEL) + 1e-6f);
    float4 wv = ((const float4*)w)[t];
    float4 o = make_float4(s.x*inv*wv.x, s.y*inv*wv.y, s.z*inv*wv.z, s.w*inv*wv.w);
    ((float4*)(out + (size_t)row*DMODEL))[t] = o;
}

// ---------------- instance norm over sequence dim ----------------
__global__ __launch_bounds__(256) void in1_kernel(
    const float* __restrict__ hh, const float* __restrict__ ffn,
    float* __restrict__ y, float* __restrict__ psum, float* __restrict__ psq)
{
    int b = blockIdx.y, chunk = blockIdx.x;
    int s0 = chunk * 32;
    int t = threadIdx.x;
    float s_[2] = {0.f, 0.f}, q_[2] = {0.f, 0.f};
    for (int s = 0; s < 32; ++s) {
        size_t base = ((size_t)(b*SEQ + s0 + s))*DMODEL;
        #pragma unroll
        for (int u = 0; u < 2; ++u) {
            int d = t + u*256;
            float yv = hh[base + d] + ffn[base + d];
            y[base + d] = yv;
            s_[u] += yv; q_[u] += yv*yv;
        }
    }
    #pragma unroll
    for (int u = 0; u < 2; ++u) {
        size_t pidx = ((size_t)b*32 + chunk)*DMODEL + t + u*256;
        psum[pidx] = s_[u];
        psq [pidx] = q_[u];
    }
}

__global__ void in2_kernel(const float* __restrict__ psum, const float* __restrict__ psq,
                           float* __restrict__ mean, float* __restrict__ rstd)
{
    int b = blockIdx.x, d = threadIdx.x;
    float s = 0.f, q = 0.f;
    for (int c = 0; c < 32; ++c) {
        size_t pidx = ((size_t)b*32 + c)*DMODEL + d;
        s += psum[pidx]; q += psq[pidx];
    }
    float m = s * (1.0f/SEQ);
    float v = q * (1.0f/SEQ) - m*m;
    mean[b*DMODEL + d] = m;
    rstd[b*DMODEL + d] = rsqrtf(v + 1e-5f);
}

__global__ void in3_kernel(const float* __restrict__ y, const float* __restrict__ mean,
                           const float* __restrict__ rstd, const float* __restrict__ w,
                           const float* __restrict__ bb, float* __restrict__ out)
{
    int i = blockIdx.x*blockDim.x + threadIdx.x;
    if (i < MTOT*DMODEL) {
        int d = i & (DMODEL - 1);
        int b = i >> 19;  // SEQ*DMODEL = 2^19
        float m = mean[b*DMODEL + d], r = rstd[b*DMODEL + d];
        out[i] = (y[i] - m) * r * w[d] + bb[d];
    }
}

// ---------------- launch ----------------
extern "C" void kernel_launch(void* const* d_in, const int* in_sizes, int n_in,
                              void* d_out, int out_size)
{
    (void)in_sizes; (void)n_in; (void)out_size;
    const float* x    = (const float*)d_in[0];
    const float* Wq   = (const float*)d_in[1];
    const float* bq   = (const float*)d_in[2];
    const float* Wkv  = (const float*)d_in[3];
    const float* bkv  = (const float*)d_in[4];
    const float* Wo   = (const float*)d_in[5];
    const float* bo   = (const float*)d_in[6];
    const float* rmsw = (const float*)d_in[7];
    const float* l1   = (const float*)d_in[8];
    const float* l2   = (const float*)d_in[9];
    const float* l3   = (const float*)d_in[10];
    const float* inw  = (const float*)d_in[11];
    const float* inb  = (const float*)d_in[12];
    float* out = (float*)d_out;

    float *q, *kv, *o, *att, *hbuf, *u1, *gate, *ffn, *y, *ps, *pq, *mn, *rs, *sc, *sv;
    cudaGetSymbolAddress((void**)&q,    g_q);
    cudaGetSymbolAddress((void**)&kv,   g_kv);
    cudaGetSymbolAddress((void**)&o,    g_o);
    cudaGetSymbolAddress((void**)&att,  g_att);
    cudaGetSymbolAddress((void**)&hbuf, g_h);
    cudaGetSymbolAddress((void**)&u1,   g_u1);
    cudaGetSymbolAddress((void**)&gate, g_gate);
    cudaGetSymbolAddress((void**)&ffn,  g_ffn);
    cudaGetSymbolAddress((void**)&y,    g_y);
    cudaGetSymbolAddress((void**)&ps,   g_psum);
    cudaGetSymbolAddress((void**)&pq,   g_psq);
    cudaGetSymbolAddress((void**)&mn,   g_mean);
    cudaGetSymbolAddress((void**)&rs,   g_rstd);
    cudaGetSymbolAddress((void**)&sc,   g_sc);
    cudaGetSymbolAddress((void**)&sv,   g_sinv);

    const int gemmSmem128 = (2*128*GBK + 2*B_BUF_F32) * 4;   // 67584 B
    const int gemmSmem64  = (2*64*GBK  + 2*B_BUF_F32) * 4;   // 51200 B
    cudaFuncSetAttribute(tf32gemm_kernel<128,false>, cudaFuncAttributeMaxDynamicSharedMemorySize, gemmSmem128);
    cudaFuncSetAttribute(tf32gemm_kernel<128,true>,  cudaFuncAttributeMaxDynamicSharedMemorySize, gemmSmem128);
    cudaFuncSetAttribute(tf32gemm_kernel<64,false>,  cudaFuncAttributeMaxDynamicSharedMemorySize, gemmSmem64);
    const int scoresSmem = 2*128*SST*4;                      // 69632 B
    cudaFuncSetAttribute(scores_kernel, cudaFuncAttributeMaxDynamicSharedMemorySize, scoresSmem);

    // QKV projections: small-N GEMMs use BM=64 (grid 256 fills chip); Wkv BM=128 (256 blocks)
    tf32gemm_kernel<64,false><<<dim3(DMODEL/128,   MTOT/64),  256, gemmSmem64 >>>(x, Wq,  bq,  nullptr, q,  MTOT, DMODEL,   DMODEL);
    tf32gemm_kernel<128,false><<<dim3(2*DMODEL/128, MTOT/128), 256, gemmSmem128>>>(x, Wkv, bkv, nullptr, kv, MTOT, 2*DMODEL, DMODEL);

    // sparse attention: scores -> select -> AV
    scores_kernel<<<dim3(SEQ/128, SEQ/128, BSZ*NH), 256, scoresSmem>>>(q, kv, sc);
    select_kernel<<<BSZ*NH*SEQ/8, 256>>>(sc, sv);
    av_kernel<<<dim3(SEQ/64, BSZ*NH), 256>>>(sc, kv, sv, o);

    // output projection + residual + rmsnorm
    tf32gemm_kernel<64,false><<<dim3(DMODEL/128, MTOT/64), 256, gemmSmem64>>>(o, Wo, bo, nullptr, att, MTOT, DMODEL, DMODEL);
    rms_add_kernel<<<MTOT, 128>>>(x, att, rmsw, hbuf);

    // SwiGLU FFN: u1 = h@l1; gate = silu(u1) * (h@l2) fused into l2 epilogue; big GEMMs BM=128
    tf32gemm_kernel<128,false><<<dim3(INNER_DIM/128, MTOT/128), 256, gemmSmem128>>>(hbuf, l1, nullptr, nullptr, u1,   MTOT, INNER_DIM, DMODEL);
    tf32gemm_kernel<128,true ><<<dim3(INNER_DIM/128, MTOT/128), 256, gemmSmem128>>>(hbuf, l2, nullptr, u1,      gate, MTOT, INNER_DIM, DMODEL);
    tf32gemm_kernel<64,false ><<<dim3(DMODEL/128,   MTOT/64),  256, gemmSmem64 >>>(gate, l3, nullptr, nullptr, ffn,  MTOT, DMODEL, INNER_DIM);

    // instance norm over sequence
    in1_kernel<<<dim3(32, BSZ), 256>>>(hbuf, ffn, y, ps, pq);
    in2_kernel<<<BSZ, DMODEL>>>(ps, pq, mn, rs);
    in3_kernel<<<(MTOT*DMODEL + 255)/256, 256>>>(y, mn, rs, inw, inb, out);
}

// round 13
// speedup vs baseline: 1.0484x; 1.0484x over previous
#include <cuda_runtime.h>
#include <math.h>

#define BSZ 4
#define SEQ 1024
#define DMODEL 512
#define NH 8
#define DHD 64
#define INNER_DIM 1536
#define MTOT (BSZ*SEQ)   /* 4096 */

// ---------------- scratch (device globals; no runtime allocation) ----------------
__device__ float g_q   [MTOT*DMODEL];
__device__ float g_kv  [MTOT*2*DMODEL];
__device__ float g_o   [MTOT*DMODEL];
__device__ float g_att [MTOT*DMODEL];
__device__ float g_h   [MTOT*DMODEL];
__device__ float g_u1  [MTOT*INNER_DIM];
__device__ float g_gate[MTOT*INNER_DIM];
__device__ float g_ffn [MTOT*DMODEL];
__device__ float g_y   [MTOT*DMODEL];
__device__ float g_psum[BSZ*32*DMODEL];
__device__ float g_psq [BSZ*32*DMODEL];
__device__ float g_mean[BSZ*DMODEL];
__device__ float g_rstd[BSZ*DMODEL];
__device__ float g_sc  [(size_t)BSZ*NH*SEQ*SEQ];   /* 134MB score/coef matrix */
__device__ float g_sinv[BSZ*NH*SEQ];

// ---------------- helpers ----------------
__device__ __forceinline__ unsigned f2key(float f) {
    unsigned u = __float_as_uint(f);
    return (u & 0x80000000u) ? ~u : (u | 0x80000000u);
}
__device__ __forceinline__ float key2f(unsigned k) {
    unsigned u = (k & 0x80000000u) ? (k & 0x7fffffffu) : ~k;
    return __uint_as_float(u);
}
__device__ __forceinline__ unsigned warpMaxU(unsigned v) {
    #pragma unroll
    for (int o = 16; o; o >>= 1) v = umax(v, __shfl_xor_sync(0xffffffffu, v, o));
    return v;
}
__device__ __forceinline__ int warpMaxI(int v) {
    #pragma unroll
    for (int o = 16; o; o >>= 1) v = max(v, __shfl_xor_sync(0xffffffffu, v, o));
    return v;
}
__device__ __forceinline__ float warpSum(float v) {
    #pragma unroll
    for (int o = 16; o; o >>= 1) v += __shfl_xor_sync(0xffffffffu, v, o);
    return v;
}
__device__ __forceinline__ unsigned to_tf32(float x) {
    unsigned u;
    asm("cvt.rna.tf32.f32 %0, %1;" : "=r"(u) : "f"(x));
    return u;
}
__device__ __forceinline__ float4 to_tf32x4(float4 v) {
    float4 r;
    r.x = __uint_as_float(to_tf32(v.x));
    r.y = __uint_as_float(to_tf32(v.y));
    r.z = __uint_as_float(to_tf32(v.z));
    r.w = __uint_as_float(to_tf32(v.w));
    return r;
}
__device__ __forceinline__ void ldsm4(unsigned* r, unsigned saddr) {
    asm volatile("ldmatrix.sync.aligned.m8n8.x4.shared.b16 {%0,%1,%2,%3}, [%4];"
                 : "=r"(r[0]), "=r"(r[1]), "=r"(r[2]), "=r"(r[3]) : "r"(saddr));
}
__device__ __forceinline__ void mma_tf32(float* d, const unsigned* a, const unsigned* b) {
    asm volatile(
        "mma.sync.aligned.m16n8k8.row.col.f32.tf32.tf32.f32 "
        "{%0,%1,%2,%3}, {%4,%5,%6,%7}, {%8,%9}, {%0,%1,%2,%3};"
        : "+f"(d[0]), "+f"(d[1]), "+f"(d[2]), "+f"(d[3])
        : "r"(a[0]), "r"(a[1]), "r"(a[2]), "r"(a[3]), "r"(b[0]), "r"(b[1]));
}

// ---------------- TF32 tensor-core GEMM: C[M,N] = A[M,K] @ B[K,N] ----------------
// Block tile 128x128, BK=32, 256 threads = 8 warps (2M x 4N), warp tile 64x32.
// AUX (compile-time): silu(aux)*val epilogue; else +bias.
#define GBK 32
#define A_BUF_F32 4096           /* 128*32 */
#define B_STRIDE 136             /* 128 + 8 pad */
#define B_BUF_F32 (GBK*B_STRIDE) /* 4352 */

template<bool AUX>
__global__ __launch_bounds__(256, 2) void tf32gemm_kernel(
    const float* __restrict__ A, const float* __restrict__ B,
    const float* __restrict__ bias, const float* __restrict__ aux,
    float* __restrict__ C, int M, int N, int K)
{
    extern __shared__ float gsm[];
    float* AsF = gsm;                    // 2 * 4096
    float* BsF = gsm + 2*A_BUF_F32;      // 2 * 4352
    const unsigned asBase = (unsigned)__cvta_generic_to_shared(AsF);

    const int tid = threadIdx.x, lane = tid & 31, wid = tid >> 5;
    const int warpM = wid & 1, warpN = wid >> 1;
    const int bm = blockIdx.y * 128, bn = blockIdx.x * 128;

    const int mbase = warpM*64 + ((lane>>3)&1)*8 + (lane&7);
    const int jhi   = lane >> 4;
    const int xorv  = lane & 7;
    const int kb    = lane & 3;
    const int nbase = warpN*32 + (lane>>2);

    float acc[4][4][4];
    #pragma unroll
    for (int mt = 0; mt < 4; ++mt)
        #pragma unroll
        for (int nt = 0; nt < 4; ++nt)
            #pragma unroll
            for (int i = 0; i < 4; ++i) acc[mt][nt][i] = 0.0f;

    const int am = tid >> 3, ak4 = tid & 7;
    const int bk = tid >> 5, bn4 = tid & 31;

    float4 regA[4], regB[4];
    #pragma unroll
    for (int p = 0; p < 4; ++p)
        regA[p] = *(const float4*)(A + (size_t)(bm + am + p*32)*K + ak4*4);
    #pragma unroll
    for (int p = 0; p < 4; ++p)
        regB[p] = *(const float4*)(B + (size_t)(bk + p*8)*N + bn + bn4*4);
    #pragma unroll
    for (int p = 0; p < 4; ++p) {
        int m = am + p*32;
        int unit = m*8 + (ak4 ^ (m & 7));
        *(float4*)(AsF + unit*4) = to_tf32x4(regA[p]);
    }
    #pragma unroll
    for (int p = 0; p < 4; ++p)
        *(float4*)(BsF + (bk + p*8)*B_STRIDE + bn4*4) = to_tf32x4(regB[p]);
    __syncthreads();

    const int nIter = K / GBK;
    int buf = 0;
    for (int kt = 0; kt < nIter; ++kt) {
        bool more = (kt + 1 < nIter);
        if (more) {
            int k0 = (kt+1)*GBK;
            #pragma unroll
            for (int p = 0; p < 4; ++p)
                regA[p] = *(const float4*)(A + (size_t)(bm + am + p*32)*K + k0 + ak4*4);
            #pragma unroll
            for (int p = 0; p < 4; ++p)
                regB[p] = *(const float4*)(B + (size_t)(k0 + bk + p*8)*N + bn + bn4*4);
        }

        const unsigned aBufBase = asBase + buf*(A_BUF_F32*4);
        const float* bb = BsF + buf*B_BUF_F32;
        #pragma unroll
        for (int ks = 0; ks < 4; ++ks) {
            unsigned af[4][4];
            #pragma unroll
            for (int mt = 0; mt < 4; ++mt) {
                int m = mbase + mt*16;
                int unit = m*8 + ((ks*2 + jhi) ^ xorv);
                ldsm4(af[mt], aBufBase + unit*16);
            }
            unsigned bf[4][2];
            #pragma unroll
            for (int nt = 0; nt < 4; ++nt) {
                bf[nt][0] = __float_as_uint(bb[(ks*8 + kb    )*B_STRIDE + nbase + nt*8]);
                bf[nt][1] = __float_as_uint(bb[(ks*8 + kb + 4)*B_STRIDE + nbase + nt*8]);
            }
            #pragma unroll
            for (int mt = 0; mt < 4; ++mt)
                #pragma unroll
                for (int nt = 0; nt < 4; ++nt)
                    mma_tf32(acc[mt][nt], af[mt], bf[nt]);
        }

        if (more) {
            int nb = buf ^ 1;
            float* AsW = AsF + nb*A_BUF_F32;
            float* BsW = BsF + nb*B_BUF_F32;
            #pragma unroll
            for (int p = 0; p < 4; ++p) {
                int m = am + p*32;
                int unit = m*8 + (ak4 ^ (m & 7));
                *(float4*)(AsW + unit*4) = to_tf32x4(regA[p]);
            }
            #pragma unroll
            for (int p = 0; p < 4; ++p)
                *(float4*)(BsW + (bk + p*8)*B_STRIDE + bn4*4) = to_tf32x4(regB[p]);
        }
        __syncthreads();
        buf ^= 1;
    }

    const int gr = lane >> 2, gc = (lane & 3) * 2;
    #pragma unroll
    for (int nt = 0; nt < 4; ++nt) {
        int col = bn + warpN*32 + nt*8 + gc;
        float b0v = (!AUX && bias) ? bias[col]   : 0.0f;
        float b1v = (!AUX && bias) ? bias[col+1] : 0.0f;
        #pragma unroll
        for (int mt = 0; mt < 4; ++mt) {
            int row = bm + warpM*64 + mt*16 + gr;
            float c0 = acc[mt][nt][0] + b0v, c1 = acc[mt][nt][1] + b1v;
            float c2 = acc[mt][nt][2] + b0v, c3 = acc[mt][nt][3] + b1v;
            if (AUX) {
                float2 a0 = *(const float2*)(aux + (size_t)row*N + col);
                float2 a1 = *(const float2*)(aux + (size_t)(row+8)*N + col);
                c0 *= a0.x / (1.f + __expf(-a0.x));
                c1 *= a0.y / (1.f + __expf(-a0.y));
                c2 *= a1.x / (1.f + __expf(-a1.x));
                c3 *= a1.y / (1.f + __expf(-a1.y));
            }
            *(float2*)(C + (size_t)row*N + col)     = make_float2(c0, c1);
            *(float2*)(C + (size_t)(row+8)*N + col) = make_float2(c2, c3);
        }
    }
}

// ---------------- attention stage 1: scores S[bh,i,t] = (q_i . k_t)/8 ----------------
// grid (SEQ/128 t-tiles, SEQ/128 i-tiles, BSZ*NH), 256 threads
#define SST 68
__global__ __launch_bounds__(256) void scores_kernel(
    const float* __restrict__ qb, const float* __restrict__ kvb, float* __restrict__ scb)
{
    extern __shared__ float smem[];
    float* sQ = smem;            // 128*SST
    float* sK = smem + 128*SST;  // 128*SST
    const int tid = threadIdx.x, lane = tid & 31, wid = tid >> 5;
    const int bh = blockIdx.z, b = bh >> 3, h = bh & 7;
    const int i0 = blockIdx.y * 128, t0 = blockIdx.x * 128;

    #pragma unroll
    for (int p = 0; p < 8; ++p) {
        int idx = tid + p*256;
        int row = idx >> 4, c4 = (idx & 15) << 2;
        *(float4*)(sQ + row*SST + c4) =
            to_tf32x4(*(const float4*)(qb + (size_t)(b*SEQ + i0 + row)*DMODEL + h*DHD + c4));
    }
    #pragma unroll
    for (int p = 0; p < 8; ++p) {
        int idx = tid + p*256;
        int row = idx >> 4, c4 = (idx & 15) << 2;
        *(float4*)(sK + row*SST + c4) =
            to_tf32x4(*(const float4*)(kvb + (size_t)(b*SEQ + t0 + row)*(2*DMODEL) + h*DHD + c4));
    }
    __syncthreads();

    const int warpM = wid & 1, warpN = wid >> 1;   // 2 x 4 warps -> warp tile 64i x 32t
    const int g = lane >> 2, fb = lane & 3;

    float acc[4][4][4];
    #pragma unroll
    for (int mt = 0; mt < 4; ++mt)
        #pragma unroll
        for (int nt = 0; nt < 4; ++nt)
            #pragma unroll
            for (int i = 0; i < 4; ++i) acc[mt][nt][i] = 0.0f;

    #pragma unroll
    for (int ks = 0; ks < 8; ++ks) {
        unsigned af[4][4], bf[4][2];
        #pragma unroll
        for (int mt = 0; mt < 4; ++mt) {
            const float* ap = sQ + (warpM*64 + mt*16 + g)*SST + ks*8 + fb;
            af[mt][0] = __float_as_uint(ap[0]);
            af[mt][1] = __float_as_uint(ap[8*SST]);
            af[mt][2] = __float_as_uint(ap[4]);
            af[mt][3] = __float_as_uint(ap[8*SST + 4]);
        }
        #pragma unroll
        for (int nt = 0; nt < 4; ++nt) {
            const float* bp = sK + (warpN*32 + nt*8 + g)*SST + ks*8 + fb;
            bf[nt][0] = __float_as_uint(bp[0]);
            bf[nt][1] = __float_as_uint(bp[4]);
        }
        #pragma unroll
        for (int mt = 0; mt < 4; ++mt)
            #pragma unroll
            for (int nt = 0; nt < 4; ++nt)
                mma_tf32(acc[mt][nt], af[mt], bf[nt]);
    }

    #pragma unroll
    for (int mt = 0; mt < 4; ++mt) {
        int iLo = i0 + warpM*64 + mt*16 + g;
        #pragma unroll
        for (int nt = 0; nt < 4; ++nt) {
            int t = t0 + warpN*32 + nt*8 + 2*fb;
            *(float2*)(scb + ((size_t)bh*SEQ + iLo)*SEQ + t) =
                make_float2(acc[mt][nt][0]*0.125f, acc[mt][nt][1]*0.125f);
            *(float2*)(scb + ((size_t)bh*SEQ + iLo + 8)*SEQ + t) =
                make_float2(acc[mt][nt][2]*0.125f, acc[mt][nt][3]*0.125f);
        }
    }
}

// ---------------- attention stage 2: per-row softmax + top-512 + coef rewrite ----------------
// 1 warp per row, 8 rows per block; keys in smem; pass-0 histogram fused into load loop
__global__ __launch_bounds__(256, 4) void select_kernel(
    float* __restrict__ scb, float* __restrict__ sinvb)
{
    __shared__ unsigned skeys[8][1024];
    __shared__ int hist[8*256];
    const int tid = threadIdx.x, lane = tid & 31, wid = tid >> 5;
    const int r = blockIdx.x*8 + wid;
    float* row = scb + (size_t)r*SEQ;
    unsigned* keys = skeys[wid];
    int* wh = hist + wid*256;

    // zero pass-0 histogram, then load scores -> keys while histogramming top byte
    #pragma unroll
    for (int i = 0; i < 8; ++i) wh[lane*8 + i] = 0;
    __syncwarp();
    unsigned mk = 0;
    #pragma unroll
    for (int j = 0; j < 32; ++j) {
        unsigned key = f2key(row[j*32 + lane]);
        keys[j*32 + lane] = key;
        mk = umax(mk, key);
        unsigned digit = key >> 24;
        unsigned grp = __match_any_sync(0xffffffffu, digit);
        if (((int)__ffs(grp) - 1) == lane) wh[digit] += __popc(grp);
    }
    mk = warpMaxU(mk);
    const float m = key2f(mk);
    float z1 = 0.f;
    #pragma unroll
    for (int j = 0; j < 32; ++j)
        z1 += __expf(key2f(keys[j*32 + lane]) - m);
    z1 = warpSum(z1);
    const float invZ1 = 1.0f / z1;

    // MSB radix select (4x8-bit); pass 0 histogram already built; alive-mask pruning
    const unsigned MASKS[4]  = {0u, 0xff000000u, 0xffff0000u, 0xffffff00u};
    const int      SHIFTS[4] = {24, 16, 8, 0};
    unsigned alive = 0xffffffffu;
    unsigned prefix = 0;
    int k = SEQ/2;
    #pragma unroll
    for (int pi = 0; pi < 4; ++pi) {
        const int shift = SHIFTS[pi];
        if (pi > 0) {
            const unsigned maskHi = MASKS[pi];
            #pragma unroll
            for (int i = 0; i < 8; ++i) wh[lane*8 + i] = 0;
            __syncwarp();
            unsigned msk = alive;
            int mx = warpMaxI(__popc(msk));
            for (int it = 0; it < mx; ++it) {
                unsigned digit = 0xffffffffu;
                if (msk) {
                    int j = __ffs(msk) - 1;
                    msk &= msk - 1;
                    unsigned key = keys[j*32 + lane];
                    if (((key ^ prefix) & maskHi) == 0u) digit = (key >> shift) & 255u;
                    else alive &= ~(1u << j);
                }
                unsigned grp = __match_any_sync(0xffffffffu, digit);
                if (digit != 0xffffffffu && ((int)__ffs(grp) - 1) == lane)
                    wh[digit] += __popc(grp);
            }
        }
        __syncwarp();
        int h8[8]; int vv = 0;
        #pragma unroll
        for (int i = 0; i < 8; ++i) { h8[i] = wh[lane*8 + i]; vv += h8[i]; }
        int inc = vv;
        #pragma unroll
        for (int o = 1; o < 32; o <<= 1) {
            int tt = __shfl_down_sync(0xffffffffu, inc, o);
            if (lane + o < 32) inc += tt;
        }
        int above = inc - vv;
        int sel = -1, newk = 0;
        if (above < k && inc >= k) {
            int csum = above;
            #pragma unroll
            for (int j = 7; j >= 0; --j) {
                int hc = h8[j];
                if (csum + hc >= k) { sel = lane*8 + j; newk = k - csum; break; }
                csum += hc;
            }
        }
        unsigned bal = __ballot_sync(0xffffffffu, sel >= 0);
        int srcl = __ffs(bal) - 1;
        sel = __shfl_sync(0xffffffffu, sel, srcl);
        k   = __shfl_sync(0xffffffffu, newk, srcl);
        prefix |= ((unsigned)sel) << shift;
        __syncwarp();
    }
    const unsigned tauKey = prefix;
    const int needEq = k;

    // collect equal-to-tau indices
    if (lane == 0) wh[0] = 0;
    __syncwarp();
    unsigned eqmask = 0;
    #pragma unroll
    for (int j = 0; j < 32; ++j) {
        if (keys[j*32 + lane] == tauKey) {
            int p = atomicAdd(&wh[0], 1);
            if (p < 255) wh[1 + p] = j*32 + lane;
            eqmask |= 1u << j;
        }
    }
    __syncwarp();
    int neq = wh[0];
    int listN = neq < 255 ? neq : 255;
    float ctau = __uint_as_float(to_tf32(__expf(__expf(key2f(tauKey) - m) * invZ1)));

    // coefficient write + Z2
    float z2 = 0.f;
    #pragma unroll
    for (int j = 0; j < 32; ++j) {
        unsigned key = keys[j*32 + lane];
        float coef = 1.0f;
        if (key > tauKey)
            coef = __uint_as_float(to_tf32(__expf(__expf(key2f(key) - m) * invZ1)));
        row[j*32 + lane] = coef;
        z2 += coef;
    }
    z2 = warpSum(z2);

    // resolve ties (jax rule: earliest t kept)
    if (eqmask) {
        unsigned em = eqmask;
        while (em) {
            int j = __ffs(em) - 1;
            em &= em - 1;
            int t = j*32 + lane;
            int rank = 0;
            for (int q = 0; q < listN; ++q) rank += (wh[1 + q] < t);
            if (rank < needEq) row[t] = ctau;
        }
    }
    int keptEq = needEq < neq ? needEq : neq;
    z2 += (ctau - 1.0f) * (float)keptEq;
    if (lane == 0) sinvb[r] = 1.0f / z2;
}

// ---------------- attention stage 3: O[bh] = diag(1/Z2) * W @ V ----------------
// grid (SEQ/64 i-tiles, BSZ*NH), 256 threads; tile 64i x 64dh, k-chunks of 64, reg prefetch
#define AWST 68
#define AVST 72
__global__ __launch_bounds__(256) void av_kernel(
    const float* __restrict__ scb, const float* __restrict__ kvb,
    const float* __restrict__ sinvb, float* __restrict__ ob)
{
    __shared__ float sW[64*AWST];
    __shared__ float sV[64*AVST];
    const int tid = threadIdx.x, lane = tid & 31, wid = tid >> 5;
    const int bh = blockIdx.y, b = bh >> 3, h = bh & 7;
    const int i0 = blockIdx.x * 64;
    const int warpM = wid & 1, warpN = wid >> 1;   // warp tile 32i x 16dh
    const int g = lane >> 2, fb = lane & 3;

    const int ldRow = tid >> 4, ldC4 = (tid & 15) << 2;   // 16 rows per pass, 4 passes

    float acc[2][2][4];
    #pragma unroll
    for (int mt = 0; mt < 2; ++mt)
        #pragma unroll
        for (int nt = 0; nt < 2; ++nt)
            #pragma unroll
            for (int i = 0; i < 4; ++i) acc[mt][nt][i] = 0.0f;

    float4 pW[4], pV[4];
    #pragma unroll
    for (int p = 0; p < 4; ++p) {
        int rowi = ldRow + p*16;
        pW[p] = *(const float4*)(scb + ((size_t)bh*SEQ + i0 + rowi)*SEQ + ldC4);
        pV[p] = to_tf32x4(*(const float4*)(kvb + (size_t)(b*SEQ + rowi)*(2*DMODEL) + DMODEL + h*DHD + ldC4));
    }

    for (int c = 0; c < SEQ/64; ++c) {
        #pragma unroll
        for (int p = 0; p < 4; ++p) {
            int rowi = ldRow + p*16;
            *(float4*)(sW + rowi*AWST + ldC4) = pW[p];
            *(float4*)(sV + rowi*AVST + ldC4) = pV[p];
        }
        __syncthreads();
        if (c + 1 < SEQ/64) {
            #pragma unroll
            for (int p = 0; p < 4; ++p) {
                int rowi = ldRow + p*16;
                pW[p] = *(const float4*)(scb + ((size_t)bh*SEQ + i0 + rowi)*SEQ + (c+1)*64 + ldC4);
                pV[p] = to_tf32x4(*(const float4*)(kvb + (size_t)(b*SEQ + (c+1)*64 + rowi)*(2*DMODEL) + DMODEL + h*DHD + ldC4));
            }
        }

        #pragma unroll
        for (int ks = 0; ks < 8; ++ks) {
            unsigned af[2][4], bf[2][2];
            #pragma unroll
            for (int mt = 0; mt < 2; ++mt) {
                const float* ap = sW + (warpM*32 + mt*16 + g)*AWST + ks*8 + fb;
                af[mt][0] = __float_as_uint(ap[0]);
                af[mt][1] = __float_as_uint(ap[8*AWST]);
                af[mt][2] = __float_as_uint(ap[4]);
                af[mt][3] = __float_as_uint(ap[8*AWST + 4]);
            }
            #pragma unroll
            for (int nt = 0; nt < 2; ++nt) {
                const float* bp = sV + (ks*8 + fb)*AVST + warpN*16 + nt*8 + g;
                bf[nt][0] = __float_as_uint(bp[0]);
                bf[nt][1] = __float_as_uint(bp[4*AVST]);
            }
            #pragma unroll
            for (int mt = 0; mt < 2; ++mt)
                #pragma unroll
                for (int nt = 0; nt < 2; ++nt)
                    mma_tf32(acc[mt][nt], af[mt], bf[nt]);
        }
        __syncthreads();
    }

    #pragma unroll
    for (int mt = 0; mt < 2; ++mt) {
        int iLo = i0 + warpM*32 + mt*16 + g;
        int iHi = iLo + 8;
        float zLo = sinvb[bh*SEQ + iLo];
        float zHi = sinvb[bh*SEQ + iHi];
        #pragma unroll
        for (int nt = 0; nt < 2; ++nt) {
            int col = h*DHD + warpN*16 + nt*8 + 2*fb;
            *(float2*)(ob + (size_t)(b*SEQ + iLo)*DMODEL + col) =
                make_float2(acc[mt][nt][0]*zLo, acc[mt][nt][1]*zLo);
            *(float2*)(ob + (size_t)(b*SEQ + iHi)*DMODEL + col) =
                make_float2(acc[mt][nt][2]*zHi, acc[mt][nt][3]*zHi);
        }
    }
}

// ---------------- residual + RMSNorm (per row of 512) ----------------
__global__ __launch_bounds__(128) void rms_add_kernel(
    const float* __restrict__ x, const float* __restrict__ a,
    const float* __restrict__ w, float* __restrict__ out)
{
    __shared__ float red[4];
    int row = blockIdx.x;
    int t = threadIdx.x;
    const float4* x4 = (const float4*)(x + (size_t)row*DMODEL);
    const float4* a4 = (const float4*)(a + (size_t)row*DMODEL);
    float4 xv = x4[t], av = a4[t];
    float4 s = make_float4(xv.x+av.x, xv.y+av.y, xv.z+av.z, xv.w+av.w);
    float ss = s.x*s.x + s.y*s.y + s.z*s.z + s.w*s.w;
    ss = warpSum(ss);
    if ((t & 31) == 0) red[t >> 5] = ss;
    __syncthreads();
    float tot = red[0] + red[1] + red[2] + red[3];
    float inv = rsqrtf(tot * (1.0f/DMODEL) + 1e-6f);
    float4 wv = ((const float4*)w)[t];
    float4 o = make_float4(s.x*inv*wv.x, s.y*inv*wv.y, s.z*inv*wv.z, s.w*inv*wv.w);
    ((float4*)(out + (size_t)row*DMODEL))[t] = o;
}

// ---------------- instance norm over sequence dim ----------------
__global__ __launch_bounds__(256) void in1_kernel(
    const float* __restrict__ hh, const float* __restrict__ ffn,
    float* __restrict__ y, float* __restrict__ psum, float* __restrict__ psq)
{
    int b = blockIdx.y, chunk = blockIdx.x;
    int s0 = chunk * 32;
    int t = threadIdx.x;
    float s_[2] = {0.f, 0.f}, q_[2] = {0.f, 0.f};
    for (int s = 0; s < 32; ++s) {
        size_t base = ((size_t)(b*SEQ + s0 + s))*DMODEL;
        #pragma unroll
        for (int u = 0; u < 2; ++u) {
            int d = t + u*256;
            float yv = hh[base + d] + ffn[base + d];
            y[base + d] = yv;
            s_[u] += yv; q_[u] += yv*yv;
        }
    }
    #pragma unroll
    for (int u = 0; u < 2; ++u) {
        size_t pidx = ((size_t)b*32 + chunk)*DMODEL + t + u*256;
        psum[pidx] = s_[u];
        psq [pidx] = q_[u];
    }
}

__global__ void in2_kernel(const float* __restrict__ psum, const float* __restrict__ psq,
                           float* __restrict__ mean, float* __restrict__ rstd)
{
    int b = blockIdx.x, d = threadIdx.x;
    float s = 0.f, q = 0.f;
    for (int c = 0; c < 32; ++c) {
        size_t pidx = ((size_t)b*32 + c)*DMODEL + d;
        s += psum[pidx]; q += psq[pidx];
    }
    float m = s * (1.0f/SEQ);
    float v = q * (1.0f/SEQ) - m*m;
    mean[b*DMODEL + d] = m;
    rstd[b*DMODEL + d] = rsqrtf(v + 1e-5f);
}

__global__ void in3_kernel(const float* __restrict__ y, const float* __restrict__ mean,
                           const float* __restrict__ rstd, const float* __restrict__ w,
                           const float* __restrict__ bb, float* __restrict__ out)
{
    int i = blockIdx.x*blockDim.x + threadIdx.x;
    if (i < MTOT*DMODEL) {
        int d = i & (DMODEL - 1);
        int b = i >> 19;  // SEQ*DMODEL = 2^19
        float m = mean[b*DMODEL + d], r = rstd[b*DMODEL + d];
        out[i] = (y[i] - m) * r * w[d] + bb[d];
    }
}

// ---------------- launch ----------------
extern "C" void kernel_launch(void* const* d_in, const int* in_sizes, int n_in,
                              void* d_out, int out_size)
{
    (void)in_sizes; (void)n_in; (void)out_size;
    const float* x    = (const float*)d_in[0];
    const float* Wq   = (const float*)d_in[1];
    const float* bq   = (const float*)d_in[2];
    const float* Wkv  = (const float*)d_in[3];
    const float* bkv  = (const float*)d_in[4];
    const float* Wo   = (const float*)d_in[5];
    const float* bo   = (const float*)d_in[6];
    const float* rmsw = (const float*)d_in[7];
    const float* l1   = (const float*)d_in[8];
    const float* l2   = (const float*)d_in[9];
    const float* l3   = (const float*)d_in[10];
    const float* inw  = (const float*)d_in[11];
    const float* inb  = (const float*)d_in[12];
    float* out = (float*)d_out;

    float *q, *kv, *o, *att, *hbuf, *u1, *gate, *ffn, *y, *ps, *pq, *mn, *rs, *sc, *sv;
    cudaGetSymbolAddress((void**)&q,    g_q);
    cudaGetSymbolAddress((void**)&kv,   g_kv);
    cudaGetSymbolAddress((void**)&o,    g_o);
    cudaGetSymbolAddress((void**)&att,  g_att);
    cudaGetSymbolAddress((void**)&hbuf, g_h);
    cudaGetSymbolAddress((void**)&u1,   g_u1);
    cudaGetSymbolAddress((void**)&gate, g_gate);
    cudaGetSymbolAddress((void**)&ffn,  g_ffn);
    cudaGetSymbolAddress((void**)&y,    g_y);
    cudaGetSymbolAddress((void**)&ps,   g_psum);
    cudaGetSymbolAddress((void**)&pq,   g_psq);
    cudaGetSymbolAddress((void**)&mn,   g_mean);
    cudaGetSymbolAddress((void**)&rs,   g_rstd);
    cudaGetSymbolAddress((void**)&sc,   g_sc);
    cudaGetSymbolAddress((void**)&sv,   g_sinv);

    const int gemmSmem = (2*A_BUF_F32 + 2*B_BUF_F32) * 4;   // 67584 B
    cudaFuncSetAttribute(tf32gemm_kernel<false>, cudaFuncAttributeMaxDynamicSharedMemorySize, gemmSmem);
    cudaFuncSetAttribute(tf32gemm_kernel<true>,  cudaFuncAttributeMaxDynamicSharedMemorySize, gemmSmem);
    const int scoresSmem = 2*128*SST*4;                      // 69632 B
    cudaFuncSetAttribute(scores_kernel, cudaFuncAttributeMaxDynamicSharedMemorySize, scoresSmem);

    // QKV projections (uniform block tile 128x128 — R9 configuration)
    tf32gemm_kernel<false><<<dim3(DMODEL/128,   MTOT/128), 256, gemmSmem>>>(x, Wq,  bq,  nullptr, q,  MTOT, DMODEL,   DMODEL);
    tf32gemm_kernel<false><<<dim3(2*DMODEL/128, MTOT/128), 256, gemmSmem>>>(x, Wkv, bkv, nullptr, kv, MTOT, 2*DMODEL, DMODEL);

    // sparse attention: scores -> select -> AV
    scores_kernel<<<dim3(SEQ/128, SEQ/128, BSZ*NH), 256, scoresSmem>>>(q, kv, sc);
    select_kernel<<<BSZ*NH*SEQ/8, 256>>>(sc, sv);
    av_kernel<<<dim3(SEQ/64, BSZ*NH), 256>>>(sc, kv, sv, o);

    // output projection + residual + rmsnorm
    tf32gemm_kernel<false><<<dim3(DMODEL/128, MTOT/128), 256, gemmSmem>>>(o, Wo, bo, nullptr, att, MTOT, DMODEL, DMODEL);
    rms_add_kernel<<<MTOT, 128>>>(x, att, rmsw, hbuf);

    // SwiGLU FFN: u1 = h@l1; gate = silu(u1) * (h@l2) fused into l2 epilogue (AUX instance only)
    tf32gemm_kernel<false><<<dim3(INNER_DIM/128, MTOT/128), 256, gemmSmem>>>(hbuf, l1, nullptr, nullptr, u1,   MTOT, INNER_DIM, DMODEL);
    tf32gemm_kernel<true ><<<dim3(INNER_DIM/128, MTOT/128), 256, gemmSmem>>>(hbuf, l2, nullptr, u1,      gate, MTOT, INNER_DIM, DMODEL);
    tf32gemm_kernel<false><<<dim3(DMODEL/128,   MTOT/128), 256, gemmSmem>>>(gate, l3, nullptr, nullptr, ffn,  MTOT, DMODEL, INNER_DIM);

    // instance norm over sequence
    in1_kernel<<<dim3(32, BSZ), 256>>>(hbuf, ffn, y, ps, pq);
    in2_kernel<<<BSZ, DMODEL>>>(ps, pq, mn, rs);
    in3_kernel<<<(MTOT*DMODEL + 255)/256, 256>>>(y, mn, rs, inw, inb, out);
}

// round 14
// speedup vs baseline: 1.0966x; 1.0460x over previous
#include <cuda_runtime.h>
#include <math.h>

#define BSZ 4
#define SEQ 1024
#define DMODEL 512
#define NH 8
#define DHD 64
#define INNER_DIM 1536
#define MTOT (BSZ*SEQ)   /* 4096 */

// ---------------- scratch (device globals; no runtime allocation) ----------------
__device__ float g_q   [MTOT*DMODEL];
__device__ float g_kv  [MTOT*2*DMODEL];
__device__ float g_o   [MTOT*DMODEL];
__device__ float g_att [MTOT*DMODEL];
__device__ float g_h   [MTOT*DMODEL];
__device__ float g_gate[MTOT*INNER_DIM];
__device__ float g_ffn [MTOT*DMODEL];
__device__ float g_psum[BSZ*32*DMODEL];
__device__ float g_psq [BSZ*32*DMODEL];
__device__ float g_mean[BSZ*DMODEL];
__device__ float g_rstd[BSZ*DMODEL];
__device__ float g_sc  [(size_t)BSZ*NH*SEQ*SEQ];   /* 134MB score/coef matrix */
__device__ float g_sinv[BSZ*NH*SEQ];

// ---------------- helpers ----------------
__device__ __forceinline__ unsigned f2key(float f) {
    unsigned u = __float_as_uint(f);
    return (u & 0x80000000u) ? ~u : (u | 0x80000000u);
}
__device__ __forceinline__ float key2f(unsigned k) {
    unsigned u = (k & 0x80000000u) ? (k & 0x7fffffffu) : ~k;
    return __uint_as_float(u);
}
__device__ __forceinline__ int warpMaxI(int v) {
    #pragma unroll
    for (int o = 16; o; o >>= 1) v = max(v, __shfl_xor_sync(0xffffffffu, v, o));
    return v;
}
__device__ __forceinline__ float warpSum(float v) {
    #pragma unroll
    for (int o = 16; o; o >>= 1) v += __shfl_xor_sync(0xffffffffu, v, o);
    return v;
}
__device__ __forceinline__ unsigned to_tf32(float x) {
    unsigned u;
    asm("cvt.rna.tf32.f32 %0, %1;" : "=r"(u) : "f"(x));
    return u;
}
__device__ __forceinline__ float4 to_tf32x4(float4 v) {
    float4 r;
    r.x = __uint_as_float(to_tf32(v.x));
    r.y = __uint_as_float(to_tf32(v.y));
    r.z = __uint_as_float(to_tf32(v.z));
    r.w = __uint_as_float(to_tf32(v.w));
    return r;
}
__device__ __forceinline__ void ldsm4(unsigned* r, unsigned saddr) {
    asm volatile("ldmatrix.sync.aligned.m8n8.x4.shared.b16 {%0,%1,%2,%3}, [%4];"
                 : "=r"(r[0]), "=r"(r[1]), "=r"(r[2]), "=r"(r[3]) : "r"(saddr));
}
__device__ __forceinline__ void mma_tf32(float* d, const unsigned* a, const unsigned* b) {
    asm volatile(
        "mma.sync.aligned.m16n8k8.row.col.f32.tf32.tf32.f32 "
        "{%0,%1,%2,%3}, {%4,%5,%6,%7}, {%8,%9}, {%0,%1,%2,%3};"
        : "+f"(d[0]), "+f"(d[1]), "+f"(d[2]), "+f"(d[3])
        : "r"(a[0]), "r"(a[1]), "r"(a[2]), "r"(a[3]), "r"(b[0]), "r"(b[1]));
}
__device__ __forceinline__ float silu(float x) { return x / (1.f + __expf(-x)); }

#define GBK 32
#define A_BUF_F32 4096           /* 128*32 */
#define B_STRIDE 136             /* 128 + 8 pad */
#define B_BUF_F32 (GBK*B_STRIDE) /* 4352 */

// ---------------- generic TF32 GEMM: C[M,N] = A[M,K] @ B[K,N] (+bias) ----------------
// Block 128x128, BK=32, 256 threads (R9 configuration).
__global__ __launch_bounds__(256, 2) void tf32gemm_kernel(
    const float* __restrict__ A, const float* __restrict__ B,
    const float* __restrict__ bias, float* __restrict__ C,
    int M, int N, int K)
{
    extern __shared__ float gsm[];
    float* AsF = gsm;
    float* BsF = gsm + 2*A_BUF_F32;
    const unsigned asBase = (unsigned)__cvta_generic_to_shared(AsF);

    const int tid = threadIdx.x, lane = tid & 31, wid = tid >> 5;
    const int warpM = wid & 1, warpN = wid >> 1;
    const int bm = blockIdx.y * 128, bn = blockIdx.x * 128;

    const int mbase = warpM*64 + ((lane>>3)&1)*8 + (lane&7);
    const int jhi   = lane >> 4;
    const int xorv  = lane & 7;
    const int kb    = lane & 3;
    const int nbase = warpN*32 + (lane>>2);

    float acc[4][4][4];
    #pragma unroll
    for (int mt = 0; mt < 4; ++mt)
        #pragma unroll
        for (int nt = 0; nt < 4; ++nt)
            #pragma unroll
            for (int i = 0; i < 4; ++i) acc[mt][nt][i] = 0.0f;

    const int am = tid >> 3, ak4 = tid & 7;
    const int bk = tid >> 5, bn4 = tid & 31;

    float4 regA[4], regB[4];
    #pragma unroll
    for (int p = 0; p < 4; ++p)
        regA[p] = *(const float4*)(A + (size_t)(bm + am + p*32)*K + ak4*4);
    #pragma unroll
    for (int p = 0; p < 4; ++p)
        regB[p] = *(const float4*)(B + (size_t)(bk + p*8)*N + bn + bn4*4);
    #pragma unroll
    for (int p = 0; p < 4; ++p) {
        int m = am + p*32;
        int unit = m*8 + (ak4 ^ (m & 7));
        *(float4*)(AsF + unit*4) = to_tf32x4(regA[p]);
    }
    #pragma unroll
    for (int p = 0; p < 4; ++p)
        *(float4*)(BsF + (bk + p*8)*B_STRIDE + bn4*4) = to_tf32x4(regB[p]);
    __syncthreads();

    const int nIter = K / GBK;
    int buf = 0;
    for (int kt = 0; kt < nIter; ++kt) {
        bool more = (kt + 1 < nIter);
        if (more) {
            int k0 = (kt+1)*GBK;
            #pragma unroll
            for (int p = 0; p < 4; ++p)
                regA[p] = *(const float4*)(A + (size_t)(bm + am + p*32)*K + k0 + ak4*4);
            #pragma unroll
            for (int p = 0; p < 4; ++p)
                regB[p] = *(const float4*)(B + (size_t)(k0 + bk + p*8)*N + bn + bn4*4);
        }
        const unsigned aBufBase = asBase + buf*(A_BUF_F32*4);
        const float* bb = BsF + buf*B_BUF_F32;
        #pragma unroll
        for (int ks = 0; ks < 4; ++ks) {
            unsigned af[4][4];
            #pragma unroll
            for (int mt = 0; mt < 4; ++mt) {
                int m = mbase + mt*16;
                int unit = m*8 + ((ks*2 + jhi) ^ xorv);
                ldsm4(af[mt], aBufBase + unit*16);
            }
            unsigned bf[4][2];
            #pragma unroll
            for (int nt = 0; nt < 4; ++nt) {
                bf[nt][0] = __float_as_uint(bb[(ks*8 + kb    )*B_STRIDE + nbase + nt*8]);
                bf[nt][1] = __float_as_uint(bb[(ks*8 + kb + 4)*B_STRIDE + nbase + nt*8]);
            }
            #pragma unroll
            for (int mt = 0; mt < 4; ++mt)
                #pragma unroll
                for (int nt = 0; nt < 4; ++nt)
                    mma_tf32(acc[mt][nt], af[mt], bf[nt]);
        }
        if (more) {
            int nb = buf ^ 1;
            float* AsW = AsF + nb*A_BUF_F32;
            float* BsW = BsF + nb*B_BUF_F32;
            #pragma unroll
            for (int p = 0; p < 4; ++p) {
                int m = am + p*32;
                int unit = m*8 + (ak4 ^ (m & 7));
                *(float4*)(AsW + unit*4) = to_tf32x4(regA[p]);
            }
            #pragma unroll
            for (int p = 0; p < 4; ++p)
                *(float4*)(BsW + (bk + p*8)*B_STRIDE + bn4*4) = to_tf32x4(regB[p]);
        }
        __syncthreads();
        buf ^= 1;
    }

    const int gr = lane >> 2, gc = (lane & 3) * 2;
    #pragma unroll
    for (int nt = 0; nt < 4; ++nt) {
        int col = bn + warpN*32 + nt*8 + gc;
        float b0v = bias ? bias[col]   : 0.0f;
        float b1v = bias ? bias[col+1] : 0.0f;
        #pragma unroll
        for (int mt = 0; mt < 4; ++mt) {
            int row = bm + warpM*64 + mt*16 + gr;
            *(float2*)(C + (size_t)row*N + col)     = make_float2(acc[mt][nt][0]+b0v, acc[mt][nt][1]+b1v);
            *(float2*)(C + (size_t)(row+8)*N + col) = make_float2(acc[mt][nt][2]+b0v, acc[mt][nt][3]+b1v);
        }
    }
}

// ---------------- fused QKV GEMM: virtual N=1536 over {Wq->q, Wkv->kv} ----------------
// Region is block-uniform (bn multiple of 128; 512 % 128 == 0).
__global__ __launch_bounds__(256, 2) void qkv_gemm_kernel(
    const float* __restrict__ A,
    const float* __restrict__ Wq, const float* __restrict__ bq,
    const float* __restrict__ Wkv, const float* __restrict__ bkv,
    float* __restrict__ Q, float* __restrict__ KV)
{
    extern __shared__ float gsm[];
    float* AsF = gsm;
    float* BsF = gsm + 2*A_BUF_F32;
    const unsigned asBase = (unsigned)__cvta_generic_to_shared(AsF);

    const int tid = threadIdx.x, lane = tid & 31, wid = tid >> 5;
    const int warpM = wid & 1, warpN = wid >> 1;
    const int bm = blockIdx.y * 128;
    const int bnv = blockIdx.x * 128;

    const float* B;
    const float* bias;
    float* C;
    int Nr, cb;
    if (bnv < DMODEL) { B = Wq;  bias = bq;  C = Q;  Nr = DMODEL;   cb = bnv; }
    else              { B = Wkv; bias = bkv; C = KV; Nr = 2*DMODEL; cb = bnv - DMODEL; }

    const int K = DMODEL;
    const int mbase = warpM*64 + ((lane>>3)&1)*8 + (lane&7);
    const int jhi   = lane >> 4;
    const int xorv  = lane & 7;
    const int kb    = lane & 3;
    const int nbase = warpN*32 + (lane>>2);

    float acc[4][4][4];
    #pragma unroll
    for (int mt = 0; mt < 4; ++mt)
        #pragma unroll
        for (int nt = 0; nt < 4; ++nt)
            #pragma unroll
            for (int i = 0; i < 4; ++i) acc[mt][nt][i] = 0.0f;

    const int am = tid >> 3, ak4 = tid & 7;
    const int bk = tid >> 5, bn4 = tid & 31;

    float4 regA[4], regB[4];
    #pragma unroll
    for (int p = 0; p < 4; ++p)
        regA[p] = *(const float4*)(A + (size_t)(bm + am + p*32)*K + ak4*4);
    #pragma unroll
    for (int p = 0; p < 4; ++p)
        regB[p] = *(const float4*)(B + (size_t)(bk + p*8)*Nr + cb + bn4*4);
    #pragma unroll
    for (int p = 0; p < 4; ++p) {
        int m = am + p*32;
        int unit = m*8 + (ak4 ^ (m & 7));
        *(float4*)(AsF + unit*4) = to_tf32x4(regA[p]);
    }
    #pragma unroll
    for (int p = 0; p < 4; ++p)
        *(float4*)(BsF + (bk + p*8)*B_STRIDE + bn4*4) = to_tf32x4(regB[p]);
    __syncthreads();

    const int nIter = K / GBK;
    int buf = 0;
    for (int kt = 0; kt < nIter; ++kt) {
        bool more = (kt + 1 < nIter);
        if (more) {
            int k0 = (kt+1)*GBK;
            #pragma unroll
            for (int p = 0; p < 4; ++p)
                regA[p] = *(const float4*)(A + (size_t)(bm + am + p*32)*K + k0 + ak4*4);
            #pragma unroll
            for (int p = 0; p < 4; ++p)
                regB[p] = *(const float4*)(B + (size_t)(k0 + bk + p*8)*Nr + cb + bn4*4);
        }
        const unsigned aBufBase = asBase + buf*(A_BUF_F32*4);
        const float* bb = BsF + buf*B_BUF_F32;
        #pragma unroll
        for (int ks = 0; ks < 4; ++ks) {
            unsigned af[4][4];
            #pragma unroll
            for (int mt = 0; mt < 4; ++mt) {
                int m = mbase + mt*16;
                int unit = m*8 + ((ks*2 + jhi) ^ xorv);
                ldsm4(af[mt], aBufBase + unit*16);
            }
            unsigned bf[4][2];
            #pragma unroll
            for (int nt = 0; nt < 4; ++nt) {
                bf[nt][0] = __float_as_uint(bb[(ks*8 + kb    )*B_STRIDE + nbase + nt*8]);
                bf[nt][1] = __float_as_uint(bb[(ks*8 + kb + 4)*B_STRIDE + nbase + nt*8]);
            }
            #pragma unroll
            for (int mt = 0; mt < 4; ++mt)
                #pragma unroll
                for (int nt = 0; nt < 4; ++nt)
                    mma_tf32(acc[mt][nt], af[mt], bf[nt]);
        }
        if (more) {
            int nb = buf ^ 1;
            float* AsW = AsF + nb*A_BUF_F32;
            float* BsW = BsF + nb*B_BUF_F32;
            #pragma unroll
            for (int p = 0; p < 4; ++p) {
                int m = am + p*32;
                int unit = m*8 + (ak4 ^ (m & 7));
                *(float4*)(AsW + unit*4) = to_tf32x4(regA[p]);
            }
            #pragma unroll
            for (int p = 0; p < 4; ++p)
                *(float4*)(BsW + (bk + p*8)*B_STRIDE + bn4*4) = to_tf32x4(regB[p]);
        }
        __syncthreads();
        buf ^= 1;
    }

    const int gr = lane >> 2, gc = (lane & 3) * 2;
    #pragma unroll
    for (int nt = 0; nt < 4; ++nt) {
        int col = cb + warpN*32 + nt*8 + gc;
        float b0v = bias[col], b1v = bias[col+1];
        #pragma unroll
        for (int mt = 0; mt < 4; ++mt) {
            int row = bm + warpM*64 + mt*16 + gr;
            *(float2*)(C + (size_t)row*Nr + col)     = make_float2(acc[mt][nt][0]+b0v, acc[mt][nt][1]+b1v);
            *(float2*)(C + (size_t)(row+8)*Nr + col) = make_float2(acc[mt][nt][2]+b0v, acc[mt][nt][3]+b1v);
        }
    }
}

// ---------------- fused FFN l1+l2 GEMM: gate = silu(A@l1) * (A@l2) ----------------
// Block: 128 rows x 64 cols of BOTH u1 and u2 (shared A); writes only gate.
__global__ __launch_bounds__(256, 2) void ffn12_gemm_kernel(
    const float* __restrict__ A, const float* __restrict__ B1,
    const float* __restrict__ B2, float* __restrict__ C)
{
    extern __shared__ float gsm[];
    float* AsF = gsm;
    float* BsF = gsm + 2*A_BUF_F32;
    const unsigned asBase = (unsigned)__cvta_generic_to_shared(AsF);

    const int tid = threadIdx.x, lane = tid & 31, wid = tid >> 5;
    const int warpM = wid & 1, warpN = wid >> 1;
    const int bm = blockIdx.y * 128, bn = blockIdx.x * 64;
    const int K = DMODEL, N = INNER_DIM;

    const int mbase = warpM*64 + ((lane>>3)&1)*8 + (lane&7);
    const int jhi   = lane >> 4;
    const int xorv  = lane & 7;
    const int kb    = lane & 3;
    const int nb1   = warpN*16 + (lane>>2);   // u1 cols [0,64); u2 at +64 in smem

    float acc1[4][2][4], acc2[4][2][4];
    #pragma unroll
    for (int mt = 0; mt < 4; ++mt)
        #pragma unroll
        for (int nt = 0; nt < 2; ++nt)
            #pragma unroll
            for (int i = 0; i < 4; ++i) { acc1[mt][nt][i] = 0.0f; acc2[mt][nt][i] = 0.0f; }

    const int am = tid >> 3, ak4 = tid & 7;
    const int bk = tid >> 5, bn4 = tid & 31;
    const bool isB2 = bn4 >= 16;
    const int bc4 = (bn4 & 15) * 4;              // col within 64-wide half
    const float* Bp = isB2 ? B2 : B1;
    const int sOff = (isB2 ? 64 : 0) + bc4;

    float4 regA[4], regB[4];
    #pragma unroll
    for (int p = 0; p < 4; ++p)
        regA[p] = *(const float4*)(A + (size_t)(bm + am + p*32)*K + ak4*4);
    #pragma unroll
    for (int p = 0; p < 4; ++p)
        regB[p] = *(const float4*)(Bp + (size_t)(bk + p*8)*N + bn + bc4);
    #pragma unroll
    for (int p = 0; p < 4; ++p) {
        int m = am + p*32;
        int unit = m*8 + (ak4 ^ (m & 7));
        *(float4*)(AsF + unit*4) = to_tf32x4(regA[p]);
    }
    #pragma unroll
    for (int p = 0; p < 4; ++p)
        *(float4*)(BsF + (bk + p*8)*B_STRIDE + sOff) = to_tf32x4(regB[p]);
    __syncthreads();

    const int nIter = K / GBK;
    int buf = 0;
    for (int kt = 0; kt < nIter; ++kt) {
        bool more = (kt + 1 < nIter);
        if (more) {
            int k0 = (kt+1)*GBK;
            #pragma unroll
            for (int p = 0; p < 4; ++p)
                regA[p] = *(const float4*)(A + (size_t)(bm + am + p*32)*K + k0 + ak4*4);
            #pragma unroll
            for (int p = 0; p < 4; ++p)
                regB[p] = *(const float4*)(Bp + (size_t)(k0 + bk + p*8)*N + bn + bc4);
        }
        const unsigned aBufBase = asBase + buf*(A_BUF_F32*4);
        const float* bb = BsF + buf*B_BUF_F32;
        #pragma unroll
        for (int ks = 0; ks < 4; ++ks) {
            unsigned af[4][4];
            #pragma unroll
            for (int mt = 0; mt < 4; ++mt) {
                int m = mbase + mt*16;
                int unit = m*8 + ((ks*2 + jhi) ^ xorv);
                ldsm4(af[mt], aBufBase + unit*16);
            }
            unsigned bf1[2][2], bf2[2][2];
            #pragma unroll
            for (int nt = 0; nt < 2; ++nt) {
                bf1[nt][0] = __float_as_uint(bb[(ks*8 + kb    )*B_STRIDE + nb1 + nt*8]);
                bf1[nt][1] = __float_as_uint(bb[(ks*8 + kb + 4)*B_STRIDE + nb1 + nt*8]);
                bf2[nt][0] = __float_as_uint(bb[(ks*8 + kb    )*B_STRIDE + 64 + nb1 + nt*8]);
                bf2[nt][1] = __float_as_uint(bb[(ks*8 + kb + 4)*B_STRIDE + 64 + nb1 + nt*8]);
            }
            #pragma unroll
            for (int mt = 0; mt < 4; ++mt)
                #pragma unroll
                for (int nt = 0; nt < 2; ++nt) {
                    mma_tf32(acc1[mt][nt], af[mt], bf1[nt]);
                    mma_tf32(acc2[mt][nt], af[mt], bf2[nt]);
                }
        }
        if (more) {
            int nb = buf ^ 1;
            float* AsW = AsF + nb*A_BUF_F32;
            float* BsW = BsF + nb*B_BUF_F32;
            #pragma unroll
            for (int p = 0; p < 4; ++p) {
                int m = am + p*32;
                int unit = m*8 + (ak4 ^ (m & 7));
                *(float4*)(AsW + unit*4) = to_tf32x4(regA[p]);
            }
            #pragma unroll
            for (int p = 0; p < 4; ++p)
                *(float4*)(BsW + (bk + p*8)*B_STRIDE + sOff) = to_tf32x4(regB[p]);
        }
        __syncthreads();
        buf ^= 1;
    }

    const int gr = lane >> 2, gc = (lane & 3) * 2;
    #pragma unroll
    for (int nt = 0; nt < 2; ++nt) {
        int col = bn + warpN*16 + nt*8 + gc;
        #pragma unroll
        for (int mt = 0; mt < 4; ++mt) {
            int row = bm + warpM*64 + mt*16 + gr;
            float g0 = silu(acc1[mt][nt][0]) * acc2[mt][nt][0];
            float g1 = silu(acc1[mt][nt][1]) * acc2[mt][nt][1];
            float g2 = silu(acc1[mt][nt][2]) * acc2[mt][nt][2];
            float g3 = silu(acc1[mt][nt][3]) * acc2[mt][nt][3];
            *(float2*)(C + (size_t)row*N + col)     = make_float2(g0, g1);
            *(float2*)(C + (size_t)(row+8)*N + col) = make_float2(g2, g3);
        }
    }
}

// ---------------- attention stage 1: scores S[bh,i,t] = (q_i . k_t)/8 ----------------
#define SST 68
__global__ __launch_bounds__(256) void scores_kernel(
    const float* __restrict__ qb, const float* __restrict__ kvb, float* __restrict__ scb)
{
    extern __shared__ float smem[];
    float* sQ = smem;
    float* sK = smem + 128*SST;
    const int tid = threadIdx.x, lane = tid & 31, wid = tid >> 5;
    const int bh = blockIdx.z, b = bh >> 3, h = bh & 7;
    const int i0 = blockIdx.y * 128, t0 = blockIdx.x * 128;

    #pragma unroll
    for (int p = 0; p < 8; ++p) {
        int idx = tid + p*256;
        int row = idx >> 4, c4 = (idx & 15) << 2;
        *(float4*)(sQ + row*SST + c4) =
            to_tf32x4(*(const float4*)(qb + (size_t)(b*SEQ + i0 + row)*DMODEL + h*DHD + c4));
    }
    #pragma unroll
    for (int p = 0; p < 8; ++p) {
        int idx = tid + p*256;
        int row = idx >> 4, c4 = (idx & 15) << 2;
        *(float4*)(sK + row*SST + c4) =
            to_tf32x4(*(const float4*)(kvb + (size_t)(b*SEQ + t0 + row)*(2*DMODEL) + h*DHD + c4));
    }
    __syncthreads();

    const int warpM = wid & 1, warpN = wid >> 1;
    const int g = lane >> 2, fb = lane & 3;

    float acc[4][4][4];
    #pragma unroll
    for (int mt = 0; mt < 4; ++mt)
        #pragma unroll
        for (int nt = 0; nt < 4; ++nt)
            #pragma unroll
            for (int i = 0; i < 4; ++i) acc[mt][nt][i] = 0.0f;

    #pragma unroll
    for (int ks = 0; ks < 8; ++ks) {
        unsigned af[4][4], bf[4][2];
        #pragma unroll
        for (int mt = 0; mt < 4; ++mt) {
            const float* ap = sQ + (warpM*64 + mt*16 + g)*SST + ks*8 + fb;
            af[mt][0] = __float_as_uint(ap[0]);
            af[mt][1] = __float_as_uint(ap[8*SST]);
            af[mt][2] = __float_as_uint(ap[4]);
            af[mt][3] = __float_as_uint(ap[8*SST + 4]);
        }
        #pragma unroll
        for (int nt = 0; nt < 4; ++nt) {
            const float* bp = sK + (warpN*32 + nt*8 + g)*SST + ks*8 + fb;
            bf[nt][0] = __float_as_uint(bp[0]);
            bf[nt][1] = __float_as_uint(bp[4]);
        }
        #pragma unroll
        for (int mt = 0; mt < 4; ++mt)
            #pragma unroll
            for (int nt = 0; nt < 4; ++nt)
                mma_tf32(acc[mt][nt], af[mt], bf[nt]);
    }

    #pragma unroll
    for (int mt = 0; mt < 4; ++mt) {
        int iLo = i0 + warpM*64 + mt*16 + g;
        #pragma unroll
        for (int nt = 0; nt < 4; ++nt) {
            int t = t0 + warpN*32 + nt*8 + 2*fb;
            *(float2*)(scb + ((size_t)bh*SEQ + iLo)*SEQ + t) =
                make_float2(acc[mt][nt][0]*0.125f, acc[mt][nt][1]*0.125f);
            *(float2*)(scb + ((size_t)bh*SEQ + iLo + 8)*SEQ + t) =
                make_float2(acc[mt][nt][2]*0.125f, acc[mt][nt][3]*0.125f);
        }
    }
}

// ---------------- attention stage 2: softmax + top-512 + coef rewrite ----------------
// No max-subtraction (softmax is shift-invariant; |s| small). z1 fused into load pass.
__global__ __launch_bounds__(256, 4) void select_kernel(
    float* __restrict__ scb, float* __restrict__ sinvb)
{
    __shared__ unsigned skeys[8][1024];
    __shared__ int hist[8*256];
    const int tid = threadIdx.x, lane = tid & 31, wid = tid >> 5;
    const int r = blockIdx.x*8 + wid;
    float* row = scb + (size_t)r*SEQ;
    unsigned* keys = skeys[wid];
    int* wh = hist + wid*256;

    // load: keys + z1 + pass-0 histogram in one pass
    #pragma unroll
    for (int i = 0; i < 8; ++i) wh[lane*8 + i] = 0;
    __syncwarp();
    float z1 = 0.f;
    #pragma unroll
    for (int j = 0; j < 32; ++j) {
        float s = row[j*32 + lane];
        unsigned key = f2key(s);
        keys[j*32 + lane] = key;
        z1 += __expf(s);
        unsigned digit = key >> 24;
        unsigned grp = __match_any_sync(0xffffffffu, digit);
        if (((int)__ffs(grp) - 1) == lane) wh[digit] += __popc(grp);
    }
    z1 = warpSum(z1);
    const float invZ1 = 1.0f / z1;

    // MSB radix select (4x8-bit); pass 0 histogram built; alive-mask pruning
    const unsigned MASKS[4]  = {0u, 0xff000000u, 0xffff0000u, 0xffffff00u};
    const int      SHIFTS[4] = {24, 16, 8, 0};
    unsigned alive = 0xffffffffu;
    unsigned prefix = 0;
    int k = SEQ/2;
    #pragma unroll
    for (int pi = 0; pi < 4; ++pi) {
        const int shift = SHIFTS[pi];
        if (pi > 0) {
            const unsigned maskHi = MASKS[pi];
            #pragma unroll
            for (int i = 0; i < 8; ++i) wh[lane*8 + i] = 0;
            __syncwarp();
            unsigned msk = alive;
            int mx = warpMaxI(__popc(msk));
            for (int it = 0; it < mx; ++it) {
                unsigned digit = 0xffffffffu;
                if (msk) {
                    int j = __ffs(msk) - 1;
                    msk &= msk - 1;
                    unsigned key = keys[j*32 + lane];
                    if (((key ^ prefix) & maskHi) == 0u) digit = (key >> shift) & 255u;
                    else alive &= ~(1u << j);
                }
                unsigned grp = __match_any_sync(0xffffffffu, digit);
                if (digit != 0xffffffffu && ((int)__ffs(grp) - 1) == lane)
                    wh[digit] += __popc(grp);
            }
        }
        __syncwarp();
        int h8[8]; int vv = 0;
        #pragma unroll
        for (int i = 0; i < 8; ++i) { h8[i] = wh[lane*8 + i]; vv += h8[i]; }
        int inc = vv;
        #pragma unroll
        for (int o = 1; o < 32; o <<= 1) {
            int tt = __shfl_down_sync(0xffffffffu, inc, o);
            if (lane + o < 32) inc += tt;
        }
        int above = inc - vv;
        int sel = -1, newk = 0;
        if (above < k && inc >= k) {
            int csum = above;
            #pragma unroll
            for (int j = 7; j >= 0; --j) {
                int hc = h8[j];
                if (csum + hc >= k) { sel = lane*8 + j; newk = k - csum; break; }
                csum += hc;
            }
        }
        unsigned bal = __ballot_sync(0xffffffffu, sel >= 0);
        int srcl = __ffs(bal) - 1;
        sel = __shfl_sync(0xffffffffu, sel, srcl);
        k   = __shfl_sync(0xffffffffu, newk, srcl);
        prefix |= ((unsigned)sel) << shift;
        __syncwarp();
    }
    const unsigned tauKey = prefix;
    const int needEq = k;

    // collect equal-to-tau indices
    if (lane == 0) wh[0] = 0;
    __syncwarp();
    unsigned eqmask = 0;
    #pragma unroll
    for (int j = 0; j < 32; ++j) {
        if (keys[j*32 + lane] == tauKey) {
            int p = atomicAdd(&wh[0], 1);
            if (p < 255) wh[1 + p] = j*32 + lane;
            eqmask |= 1u << j;
        }
    }
    __syncwarp();
    int neq = wh[0];
    int listN = neq < 255 ? neq : 255;
    float ctau = __uint_as_float(to_tf32(__expf(__expf(key2f(tauKey)) * invZ1)));

    // coefficient write + Z2
    float z2 = 0.f;
    #pragma unroll
    for (int j = 0; j < 32; ++j) {
        unsigned key = keys[j*32 + lane];
        float coef = 1.0f;
        if (key > tauKey)
            coef = __uint_as_float(to_tf32(__expf(__expf(key2f(key)) * invZ1)));
        row[j*32 + lane] = coef;
        z2 += coef;
    }
    z2 = warpSum(z2);

    // resolve ties (jax rule: earliest t kept)
    if (eqmask) {
        unsigned em = eqmask;
        while (em) {
            int j = __ffs(em) - 1;
            em &= em - 1;
            int t = j*32 + lane;
            int rank = 0;
            for (int q = 0; q < listN; ++q) rank += (wh[1 + q] < t);
            if (rank < needEq) row[t] = ctau;
        }
    }
    int keptEq = needEq < neq ? needEq : neq;
    z2 += (ctau - 1.0f) * (float)keptEq;
    if (lane == 0) sinvb[r] = 1.0f / z2;
}

// ---------------- attention stage 3: O[bh] = diag(1/Z2) * W @ V ----------------
#define AWST 68
#define AVST 72
__global__ __launch_bounds__(256) void av_kernel(
    const float* __restrict__ scb, const float* __restrict__ kvb,
    const float* __restrict__ sinvb, float* __restrict__ ob)
{
    __shared__ float sW[64*AWST];
    __shared__ float sV[64*AVST];
    const int tid = threadIdx.x, lane = tid & 31, wid = tid >> 5;
    const int bh = blockIdx.y, b = bh >> 3, h = bh & 7;
    const int i0 = blockIdx.x * 64;
    const int warpM = wid & 1, warpN = wid >> 1;
    const int g = lane >> 2, fb = lane & 3;

    const int ldRow = tid >> 4, ldC4 = (tid & 15) << 2;

    float acc[2][2][4];
    #pragma unroll
    for (int mt = 0; mt < 2; ++mt)
        #pragma unroll
        for (int nt = 0; nt < 2; ++nt)
            #pragma unroll
            for (int i = 0; i < 4; ++i) acc[mt][nt][i] = 0.0f;

    float4 pW[4], pV[4];
    #pragma unroll
    for (int p = 0; p < 4; ++p) {
        int rowi = ldRow + p*16;
        pW[p] = *(const float4*)(scb + ((size_t)bh*SEQ + i0 + rowi)*SEQ + ldC4);
        pV[p] = to_tf32x4(*(const float4*)(kvb + (size_t)(b*SEQ + rowi)*(2*DMODEL) + DMODEL + h*DHD + ldC4));
    }

    for (int c = 0; c < SEQ/64; ++c) {
        #pragma unroll
        for (int p = 0; p < 4; ++p) {
            int rowi = ldRow + p*16;
            *(float4*)(sW + rowi*AWST + ldC4) = pW[p];
            *(float4*)(sV + rowi*AVST + ldC4) = pV[p];
        }
        __syncthreads();
        if (c + 1 < SEQ/64) {
            #pragma unroll
            for (int p = 0; p < 4; ++p) {
                int rowi = ldRow + p*16;
                pW[p] = *(const float4*)(scb + ((size_t)bh*SEQ + i0 + rowi)*SEQ + (c+1)*64 + ldC4);
                pV[p] = to_tf32x4(*(const float4*)(kvb + (size_t)(b*SEQ + (c+1)*64 + rowi)*(2*DMODEL) + DMODEL + h*DHD + ldC4));
            }
        }

        #pragma unroll
        for (int ks = 0; ks < 8; ++ks) {
            unsigned af[2][4], bf[2][2];
            #pragma unroll
            for (int mt = 0; mt < 2; ++mt) {
                const float* ap = sW + (warpM*32 + mt*16 + g)*AWST + ks*8 + fb;
                af[mt][0] = __float_as_uint(ap[0]);
                af[mt][1] = __float_as_uint(ap[8*AWST]);
                af[mt][2] = __float_as_uint(ap[4]);
                af[mt][3] = __float_as_uint(ap[8*AWST + 4]);
            }
            #pragma unroll
            for (int nt = 0; nt < 2; ++nt) {
                const float* bp = sV + (ks*8 + fb)*AVST + warpN*16 + nt*8 + g;
                bf[nt][0] = __float_as_uint(bp[0]);
                bf[nt][1] = __float_as_uint(bp[4*AVST]);
            }
            #pragma unroll
            for (int mt = 0; mt < 2; ++mt)
                #pragma unroll
                for (int nt = 0; nt < 2; ++nt)
                    mma_tf32(acc[mt][nt], af[mt], bf[nt]);
        }
        __syncthreads();
    }

    #pragma unroll
    for (int mt = 0; mt < 2; ++mt) {
        int iLo = i0 + warpM*32 + mt*16 + g;
        int iHi = iLo + 8;
        float zLo = sinvb[bh*SEQ + iLo];
        float zHi = sinvb[bh*SEQ + iHi];
        #pragma unroll
        for (int nt = 0; nt < 2; ++nt) {
            int col = h*DHD + warpN*16 + nt*8 + 2*fb;
            *(float2*)(ob + (size_t)(b*SEQ + iLo)*DMODEL + col) =
                make_float2(acc[mt][nt][0]*zLo, acc[mt][nt][1]*zLo);
            *(float2*)(ob + (size_t)(b*SEQ + iHi)*DMODEL + col) =
                make_float2(acc[mt][nt][2]*zHi, acc[mt][nt][3]*zHi);
        }
    }
}

// ---------------- residual + RMSNorm ----------------
__global__ __launch_bounds__(128) void rms_add_kernel(
    const float* __restrict__ x, const float* __restrict__ a,
    const float* __restrict__ w, float* __restrict__ out)
{
    __shared__ float red[4];
    int row = blockIdx.x;
    int t = threadIdx.x;
    const float4* x4 = (const float4*)(x + (size_t)row*DMODEL);
    const float4* a4 = (const float4*)(a + (size_t)row*DMODEL);
    float4 xv = x4[t], av = a4[t];
    float4 s = make_float4(xv.x+av.x, xv.y+av.y, xv.z+av.z, xv.w+av.w);
    float ss = s.x*s.x + s.y*s.y + s.z*s.z + s.w*s.w;
    ss = warpSum(ss);
    if ((t & 31) == 0) red[t >> 5] = ss;
    __syncthreads();
    float tot = red[0] + red[1] + red[2] + red[3];
    float inv = rsqrtf(tot * (1.0f/DMODEL) + 1e-6f);
    float4 wv = ((const float4*)w)[t];
    ((float4*)(out + (size_t)row*DMODEL))[t] =
        make_float4(s.x*inv*wv.x, s.y*inv*wv.y, s.z*inv*wv.z, s.w*inv*wv.w);
}

// ---------------- instance norm over sequence dim (no y buffer) ----------------
__global__ __launch_bounds__(256) void in1_kernel(
    const float* __restrict__ hh, const float* __restrict__ ffn,
    float* __restrict__ psum, float* __restrict__ psq)
{
    int b = blockIdx.y, chunk = blockIdx.x;
    int s0 = chunk * 32;
    int t = threadIdx.x;
    float s_[2] = {0.f, 0.f}, q_[2] = {0.f, 0.f};
    for (int s = 0; s < 32; ++s) {
        size_t base = ((size_t)(b*SEQ + s0 + s))*DMODEL;
        #pragma unroll
        for (int u = 0; u < 2; ++u) {
            int d = t + u*256;
            float yv = hh[base + d] + ffn[base + d];
            s_[u] += yv; q_[u] += yv*yv;
        }
    }
    #pragma unroll
    for (int u = 0; u < 2; ++u) {
        size_t pidx = ((size_t)b*32 + chunk)*DMODEL + t + u*256;
        psum[pidx] = s_[u];
        psq [pidx] = q_[u];
    }
}

__global__ void in2_kernel(const float* __restrict__ psum, const float* __restrict__ psq,
                           float* __restrict__ mean, float* __restrict__ rstd)
{
    int b = blockIdx.x, d = threadIdx.x;
    float s = 0.f, q = 0.f;
    for (int c = 0; c < 32; ++c) {
        size_t pidx = ((size_t)b*32 + c)*DMODEL + d;
        s += psum[pidx]; q += psq[pidx];
    }
    float m = s * (1.0f/SEQ);
    float v = q * (1.0f/SEQ) - m*m;
    mean[b*DMODEL + d] = m;
    rstd[b*DMODEL + d] = rsqrtf(v + 1e-5f);
}

__global__ void in3_kernel(const float* __restrict__ hh, const float* __restrict__ ffn,
                           const float* __restrict__ mean, const float* __restrict__ rstd,
                           const float* __restrict__ w, const float* __restrict__ bb,
                           float* __restrict__ out)
{
    int i = blockIdx.x*blockDim.x + threadIdx.x;
    if (i < MTOT*DMODEL) {
        int d = i & (DMODEL - 1);
        int b = i >> 19;  // SEQ*DMODEL = 2^19
        float m = mean[b*DMODEL + d], r = rstd[b*DMODEL + d];
        float yv = hh[i] + ffn[i];
        out[i] = (yv - m) * r * w[d] + bb[d];
    }
}

// ---------------- launch ----------------
extern "C" void kernel_launch(void* const* d_in, const int* in_sizes, int n_in,
                              void* d_out, int out_size)
{
    (void)in_sizes; (void)n_in; (void)out_size;
    const float* x    = (const float*)d_in[0];
    const float* Wq   = (const float*)d_in[1];
    const float* bq   = (const float*)d_in[2];
    const float* Wkv  = (const float*)d_in[3];
    const float* bkv  = (const float*)d_in[4];
    const float* Wo   = (const float*)d_in[5];
    const float* bo   = (const float*)d_in[6];
    const float* rmsw = (const float*)d_in[7];
    const float* l1   = (const float*)d_in[8];
    const float* l2   = (const float*)d_in[9];
    const float* l3   = (const float*)d_in[10];
    const float* inw  = (const float*)d_in[11];
    const float* inb  = (const float*)d_in[12];
    float* out = (float*)d_out;

    float *q, *kv, *o, *att, *hbuf, *gate, *ffn, *ps, *pq, *mn, *rs, *sc, *sv;
    cudaGetSymbolAddress((void**)&q,    g_q);
    cudaGetSymbolAddress((void**)&kv,   g_kv);
    cudaGetSymbolAddress((void**)&o,    g_o);
    cudaGetSymbolAddress((void**)&att,  g_att);
    cudaGetSymbolAddress((void**)&hbuf, g_h);
    cudaGetSymbolAddress((void**)&gate, g_gate);
    cudaGetSymbolAddress((void**)&ffn,  g_ffn);
    cudaGetSymbolAddress((void**)&ps,   g_psum);
    cudaGetSymbolAddress((void**)&pq,   g_psq);
    cudaGetSymbolAddress((void**)&mn,   g_mean);
    cudaGetSymbolAddress((void**)&rs,   g_rstd);
    cudaGetSymbolAddress((void**)&sc,   g_sc);
    cudaGetSymbolAddress((void**)&sv,   g_sinv);

    const int gemmSmem = (2*A_BUF_F32 + 2*B_BUF_F32) * 4;   // 67584 B
    cudaFuncSetAttribute(tf32gemm_kernel,  cudaFuncAttributeMaxDynamicSharedMemorySize, gemmSmem);
    cudaFuncSetAttribute(qkv_gemm_kernel,  cudaFuncAttributeMaxDynamicSharedMemorySize, gemmSmem);
    cudaFuncSetAttribute(ffn12_gemm_kernel, cudaFuncAttributeMaxDynamicSharedMemorySize, gemmSmem);
    const int scoresSmem = 2*128*SST*4;                      // 69632 B
    cudaFuncSetAttribute(scores_kernel, cudaFuncAttributeMaxDynamicSharedMemorySize, scoresSmem);

    // fused QKV projection (virtual N = 1536 -> 384 blocks)
    qkv_gemm_kernel<<<dim3(3*DMODEL/128, MTOT/128), 256, gemmSmem>>>(x, Wq, bq, Wkv, bkv, q, kv);

    // sparse attention: scores -> select -> AV
    scores_kernel<<<dim3(SEQ/128, SEQ/128, BSZ*NH), 256, scoresSmem>>>(q, kv, sc);
    select_kernel<<<BSZ*NH*SEQ/8, 256>>>(sc, sv);
    av_kernel<<<dim3(SEQ/64, BSZ*NH), 256>>>(sc, kv, sv, o);

    // output projection + residual + rmsnorm
    tf32gemm_kernel<<<dim3(DMODEL/128, MTOT/128), 256, gemmSmem>>>(o, Wo, bo, att, MTOT, DMODEL, DMODEL);
    rms_add_kernel<<<MTOT, 128>>>(x, att, rmsw, hbuf);

    // SwiGLU FFN: gate = silu(h@l1) * (h@l2) in ONE launch; then l3
    ffn12_gemm_kernel<<<dim3(INNER_DIM/64, MTOT/128), 256, gemmSmem>>>(hbuf, l1, l2, gate);
    tf32gemm_kernel<<<dim3(DMODEL/128, MTOT/128), 256, gemmSmem>>>(gate, l3, nullptr, ffn, MTOT, DMODEL, INNER_DIM);

    // instance norm over sequence (y recomputed in in3; no y buffer)
    in1_kernel<<<dim3(32, BSZ), 256>>>(hbuf, ffn, ps, pq);
    in2_kernel<<<BSZ, DMODEL>>>(ps, pq, mn, rs);
    in3_kernel<<<(MTOT*DMODEL + 255)/256, 256>>>(hbuf, ffn, mn, rs, inw, inb, out);
}

// round 15
// speedup vs baseline: 1.1090x; 1.0113x over previous
#include <cuda_runtime.h>
#include <math.h>

#define BSZ 4
#define SEQ 1024
#define DMODEL 512
#define NH 8
#define DHD 64
#define INNER_DIM 1536
#define MTOT (BSZ*SEQ)   /* 4096 */

// ---------------- scratch (device globals; no runtime allocation) ----------------
__device__ float g_q   [MTOT*DMODEL];
__device__ float g_kv  [MTOT*2*DMODEL];
__device__ float g_o   [MTOT*DMODEL];
__device__ float g_att [MTOT*DMODEL];
__device__ float g_h   [MTOT*DMODEL];
__device__ float g_gate[MTOT*INNER_DIM];
__device__ float g_ffn [MTOT*DMODEL];
__device__ float g_psum[BSZ*32*DMODEL];
__device__ float g_psq [BSZ*32*DMODEL];
__device__ float g_mean[BSZ*DMODEL];
__device__ float g_rstd[BSZ*DMODEL];
__device__ float g_sc  [(size_t)BSZ*NH*SEQ*SEQ];   /* 134MB score/coef matrix */
__device__ float g_sinv[BSZ*NH*SEQ];

// ---------------- helpers ----------------
__device__ __forceinline__ unsigned f2key(float f) {
    unsigned u = __float_as_uint(f);
    return (u & 0x80000000u) ? ~u : (u | 0x80000000u);
}
__device__ __forceinline__ float key2f(unsigned k) {
    unsigned u = (k & 0x80000000u) ? (k & 0x7fffffffu) : ~k;
    return __uint_as_float(u);
}
__device__ __forceinline__ int warpMaxI(int v) {
    #pragma unroll
    for (int o = 16; o; o >>= 1) v = max(v, __shfl_xor_sync(0xffffffffu, v, o));
    return v;
}
__device__ __forceinline__ float warpSum(float v) {
    #pragma unroll
    for (int o = 16; o; o >>= 1) v += __shfl_xor_sync(0xffffffffu, v, o);
    return v;
}
__device__ __forceinline__ unsigned to_tf32(float x) {
    unsigned u;
    asm("cvt.rna.tf32.f32 %0, %1;" : "=r"(u) : "f"(x));
    return u;
}
__device__ __forceinline__ float4 to_tf32x4(float4 v) {
    float4 r;
    r.x = __uint_as_float(to_tf32(v.x));
    r.y = __uint_as_float(to_tf32(v.y));
    r.z = __uint_as_float(to_tf32(v.z));
    r.w = __uint_as_float(to_tf32(v.w));
    return r;
}
__device__ __forceinline__ void ldsm4(unsigned* r, unsigned saddr) {
    asm volatile("ldmatrix.sync.aligned.m8n8.x4.shared.b16 {%0,%1,%2,%3}, [%4];"
                 : "=r"(r[0]), "=r"(r[1]), "=r"(r[2]), "=r"(r[3]) : "r"(saddr));
}
__device__ __forceinline__ void mma_tf32(float* d, const unsigned* a, const unsigned* b) {
    asm volatile(
        "mma.sync.aligned.m16n8k8.row.col.f32.tf32.tf32.f32 "
        "{%0,%1,%2,%3}, {%4,%5,%6,%7}, {%8,%9}, {%0,%1,%2,%3};"
        : "+f"(d[0]), "+f"(d[1]), "+f"(d[2]), "+f"(d[3])
        : "r"(a[0]), "r"(a[1]), "r"(a[2]), "r"(a[3]), "r"(b[0]), "r"(b[1]));
}
__device__ __forceinline__ float silu(float x) { return x / (1.f + __expf(-x)); }
__device__ __forceinline__ void cp_async16(unsigned saddr, const void* gaddr) {
    asm volatile("cp.async.cg.shared.global [%0], [%1], 16;" :: "r"(saddr), "l"(gaddr));
}
__device__ __forceinline__ void cp_commit() {
    asm volatile("cp.async.commit_group;");
}
template<int N>
__device__ __forceinline__ void cp_wait() {
    asm volatile("cp.async.wait_group %0;" :: "n"(N));
}

#define GBK 32
#define A_BUF_F32 4096           /* 128*32 */
#define B_STRIDE 136             /* 128 + 8 pad */
#define B_BUF_F32 (GBK*B_STRIDE) /* 4352 */

// ---------------- generic TF32 GEMM: C[M,N] = A[M,K] @ B[K,N] (+bias) ----------------
__global__ __launch_bounds__(256, 2) void tf32gemm_kernel(
    const float* __restrict__ A, const float* __restrict__ B,
    const float* __restrict__ bias, float* __restrict__ C,
    int M, int N, int K)
{
    extern __shared__ float gsm[];
    float* AsF = gsm;
    float* BsF = gsm + 2*A_BUF_F32;
    const unsigned asBase = (unsigned)__cvta_generic_to_shared(AsF);

    const int tid = threadIdx.x, lane = tid & 31, wid = tid >> 5;
    const int warpM = wid & 1, warpN = wid >> 1;
    const int bm = blockIdx.y * 128, bn = blockIdx.x * 128;

    const int mbase = warpM*64 + ((lane>>3)&1)*8 + (lane&7);
    const int jhi   = lane >> 4;
    const int xorv  = lane & 7;
    const int kb    = lane & 3;
    const int nbase = warpN*32 + (lane>>2);

    float acc[4][4][4];
    #pragma unroll
    for (int mt = 0; mt < 4; ++mt)
        #pragma unroll
        for (int nt = 0; nt < 4; ++nt)
            #pragma unroll
            for (int i = 0; i < 4; ++i) acc[mt][nt][i] = 0.0f;

    const int am = tid >> 3, ak4 = tid & 7;
    const int bk = tid >> 5, bn4 = tid & 31;

    float4 regA[4], regB[4];
    #pragma unroll
    for (int p = 0; p < 4; ++p)
        regA[p] = *(const float4*)(A + (size_t)(bm + am + p*32)*K + ak4*4);
    #pragma unroll
    for (int p = 0; p < 4; ++p)
        regB[p] = *(const float4*)(B + (size_t)(bk + p*8)*N + bn + bn4*4);
    #pragma unroll
    for (int p = 0; p < 4; ++p) {
        int m = am + p*32;
        int unit = m*8 + (ak4 ^ (m & 7));
        *(float4*)(AsF + unit*4) = to_tf32x4(regA[p]);
    }
    #pragma unroll
    for (int p = 0; p < 4; ++p)
        *(float4*)(BsF + (bk + p*8)*B_STRIDE + bn4*4) = to_tf32x4(regB[p]);
    __syncthreads();

    const int nIter = K / GBK;
    int buf = 0;
    for (int kt = 0; kt < nIter; ++kt) {
        bool more = (kt + 1 < nIter);
        if (more) {
            int k0 = (kt+1)*GBK;
            #pragma unroll
            for (int p = 0; p < 4; ++p)
                regA[p] = *(const float4*)(A + (size_t)(bm + am + p*32)*K + k0 + ak4*4);
            #pragma unroll
            for (int p = 0; p < 4; ++p)
                regB[p] = *(const float4*)(B + (size_t)(k0 + bk + p*8)*N + bn + bn4*4);
        }
        const unsigned aBufBase = asBase + buf*(A_BUF_F32*4);
        const float* bb = BsF + buf*B_BUF_F32;
        #pragma unroll
        for (int ks = 0; ks < 4; ++ks) {
            unsigned af[4][4];
            #pragma unroll
            for (int mt = 0; mt < 4; ++mt) {
                int m = mbase + mt*16;
                int unit = m*8 + ((ks*2 + jhi) ^ xorv);
                ldsm4(af[mt], aBufBase + unit*16);
            }
            unsigned bf[4][2];
            #pragma unroll
            for (int nt = 0; nt < 4; ++nt) {
                bf[nt][0] = __float_as_uint(bb[(ks*8 + kb    )*B_STRIDE + nbase + nt*8]);
                bf[nt][1] = __float_as_uint(bb[(ks*8 + kb + 4)*B_STRIDE + nbase + nt*8]);
            }
            #pragma unroll
            for (int mt = 0; mt < 4; ++mt)
                #pragma unroll
                for (int nt = 0; nt < 4; ++nt)
                    mma_tf32(acc[mt][nt], af[mt], bf[nt]);
        }
        if (more) {
            int nb = buf ^ 1;
            float* AsW = AsF + nb*A_BUF_F32;
            float* BsW = BsF + nb*B_BUF_F32;
            #pragma unroll
            for (int p = 0; p < 4; ++p) {
                int m = am + p*32;
                int unit = m*8 + (ak4 ^ (m & 7));
                *(float4*)(AsW + unit*4) = to_tf32x4(regA[p]);
            }
            #pragma unroll
            for (int p = 0; p < 4; ++p)
                *(float4*)(BsW + (bk + p*8)*B_STRIDE + bn4*4) = to_tf32x4(regB[p]);
        }
        __syncthreads();
        buf ^= 1;
    }

    const int gr = lane >> 2, gc = (lane & 3) * 2;
    #pragma unroll
    for (int nt = 0; nt < 4; ++nt) {
        int col = bn + warpN*32 + nt*8 + gc;
        float b0v = bias ? bias[col]   : 0.0f;
        float b1v = bias ? bias[col+1] : 0.0f;
        #pragma unroll
        for (int mt = 0; mt < 4; ++mt) {
            int row = bm + warpM*64 + mt*16 + gr;
            *(float2*)(C + (size_t)row*N + col)     = make_float2(acc[mt][nt][0]+b0v, acc[mt][nt][1]+b1v);
            *(float2*)(C + (size_t)(row+8)*N + col) = make_float2(acc[mt][nt][2]+b0v, acc[mt][nt][3]+b1v);
        }
    }
}

// ---------------- fused QKV GEMM: virtual N=1536 over {Wq->q, Wkv->kv} ----------------
__global__ __launch_bounds__(256, 2) void qkv_gemm_kernel(
    const float* __restrict__ A,
    const float* __restrict__ Wq, const float* __restrict__ bq,
    const float* __restrict__ Wkv, const float* __restrict__ bkv,
    float* __restrict__ Q, float* __restrict__ KV)
{
    extern __shared__ float gsm[];
    float* AsF = gsm;
    float* BsF = gsm + 2*A_BUF_F32;
    const unsigned asBase = (unsigned)__cvta_generic_to_shared(AsF);

    const int tid = threadIdx.x, lane = tid & 31, wid = tid >> 5;
    const int warpM = wid & 1, warpN = wid >> 1;
    const int bm = blockIdx.y * 128;
    const int bnv = blockIdx.x * 128;

    const float* B;
    const float* bias;
    float* C;
    int Nr, cb;
    if (bnv < DMODEL) { B = Wq;  bias = bq;  C = Q;  Nr = DMODEL;   cb = bnv; }
    else              { B = Wkv; bias = bkv; C = KV; Nr = 2*DMODEL; cb = bnv - DMODEL; }

    const int K = DMODEL;
    const int mbase = warpM*64 + ((lane>>3)&1)*8 + (lane&7);
    const int jhi   = lane >> 4;
    const int xorv  = lane & 7;
    const int kb    = lane & 3;
    const int nbase = warpN*32 + (lane>>2);

    float acc[4][4][4];
    #pragma unroll
    for (int mt = 0; mt < 4; ++mt)
        #pragma unroll
        for (int nt = 0; nt < 4; ++nt)
            #pragma unroll
            for (int i = 0; i < 4; ++i) acc[mt][nt][i] = 0.0f;

    const int am = tid >> 3, ak4 = tid & 7;
    const int bk = tid >> 5, bn4 = tid & 31;

    float4 regA[4], regB[4];
    #pragma unroll
    for (int p = 0; p < 4; ++p)
        regA[p] = *(const float4*)(A + (size_t)(bm + am + p*32)*K + ak4*4);
    #pragma unroll
    for (int p = 0; p < 4; ++p)
        regB[p] = *(const float4*)(B + (size_t)(bk + p*8)*Nr + cb + bn4*4);
    #pragma unroll
    for (int p = 0; p < 4; ++p) {
        int m = am + p*32;
        int unit = m*8 + (ak4 ^ (m & 7));
        *(float4*)(AsF + unit*4) = to_tf32x4(regA[p]);
    }
    #pragma unroll
    for (int p = 0; p < 4; ++p)
        *(float4*)(BsF + (bk + p*8)*B_STRIDE + bn4*4) = to_tf32x4(regB[p]);
    __syncthreads();

    const int nIter = K / GBK;
    int buf = 0;
    for (int kt = 0; kt < nIter; ++kt) {
        bool more = (kt + 1 < nIter);
        if (more) {
            int k0 = (kt+1)*GBK;
            #pragma unroll
            for (int p = 0; p < 4; ++p)
                regA[p] = *(const float4*)(A + (size_t)(bm + am + p*32)*K + k0 + ak4*4);
            #pragma unroll
            for (int p = 0; p < 4; ++p)
                regB[p] = *(const float4*)(B + (size_t)(k0 + bk + p*8)*Nr + cb + bn4*4);
        }
        const unsigned aBufBase = asBase + buf*(A_BUF_F32*4);
        const float* bb = BsF + buf*B_BUF_F32;
        #pragma unroll
        for (int ks = 0; ks < 4; ++ks) {
            unsigned af[4][4];
            #pragma unroll
            for (int mt = 0; mt < 4; ++mt) {
                int m = mbase + mt*16;
                int unit = m*8 + ((ks*2 + jhi) ^ xorv);
                ldsm4(af[mt], aBufBase + unit*16);
            }
            unsigned bf[4][2];
            #pragma unroll
            for (int nt = 0; nt < 4; ++nt) {
                bf[nt][0] = __float_as_uint(bb[(ks*8 + kb    )*B_STRIDE + nbase + nt*8]);
                bf[nt][1] = __float_as_uint(bb[(ks*8 + kb + 4)*B_STRIDE + nbase + nt*8]);
            }
            #pragma unroll
            for (int mt = 0; mt < 4; ++mt)
                #pragma unroll
                for (int nt = 0; nt < 4; ++nt)
                    mma_tf32(acc[mt][nt], af[mt], bf[nt]);
        }
        if (more) {
            int nb = buf ^ 1;
            float* AsW = AsF + nb*A_BUF_F32;
            float* BsW = BsF + nb*B_BUF_F32;
            #pragma unroll
            for (int p = 0; p < 4; ++p) {
                int m = am + p*32;
                int unit = m*8 + (ak4 ^ (m & 7));
                *(float4*)(AsW + unit*4) = to_tf32x4(regA[p]);
            }
            #pragma unroll
            for (int p = 0; p < 4; ++p)
                *(float4*)(BsW + (bk + p*8)*B_STRIDE + bn4*4) = to_tf32x4(regB[p]);
        }
        __syncthreads();
        buf ^= 1;
    }

    const int gr = lane >> 2, gc = (lane & 3) * 2;
    #pragma unroll
    for (int nt = 0; nt < 4; ++nt) {
        int col = cb + warpN*32 + nt*8 + gc;
        float b0v = bias[col], b1v = bias[col+1];
        #pragma unroll
        for (int mt = 0; mt < 4; ++mt) {
            int row = bm + warpM*64 + mt*16 + gr;
            *(float2*)(C + (size_t)row*Nr + col)     = make_float2(acc[mt][nt][0]+b0v, acc[mt][nt][1]+b1v);
            *(float2*)(C + (size_t)(row+8)*Nr + col) = make_float2(acc[mt][nt][2]+b0v, acc[mt][nt][3]+b1v);
        }
    }
}

// ---------------- fused FFN l1+l2 GEMM: gate = silu(A@l1) * (A@l2) ----------------
__global__ __launch_bounds__(256, 2) void ffn12_gemm_kernel(
    const float* __restrict__ A, const float* __restrict__ B1,
    const float* __restrict__ B2, float* __restrict__ C)
{
    extern __shared__ float gsm[];
    float* AsF = gsm;
    float* BsF = gsm + 2*A_BUF_F32;
    const unsigned asBase = (unsigned)__cvta_generic_to_shared(AsF);

    const int tid = threadIdx.x, lane = tid & 31, wid = tid >> 5;
    const int warpM = wid & 1, warpN = wid >> 1;
    const int bm = blockIdx.y * 128, bn = blockIdx.x * 64;
    const int K = DMODEL, N = INNER_DIM;

    const int mbase = warpM*64 + ((lane>>3)&1)*8 + (lane&7);
    const int jhi   = lane >> 4;
    const int xorv  = lane & 7;
    const int kb    = lane & 3;
    const int nb1   = warpN*16 + (lane>>2);

    float acc1[4][2][4], acc2[4][2][4];
    #pragma unroll
    for (int mt = 0; mt < 4; ++mt)
        #pragma unroll
        for (int nt = 0; nt < 2; ++nt)
            #pragma unroll
            for (int i = 0; i < 4; ++i) { acc1[mt][nt][i] = 0.0f; acc2[mt][nt][i] = 0.0f; }

    const int am = tid >> 3, ak4 = tid & 7;
    const int bk = tid >> 5, bn4 = tid & 31;
    const bool isB2 = bn4 >= 16;
    const int bc4 = (bn4 & 15) * 4;
    const float* Bp = isB2 ? B2 : B1;
    const int sOff = (isB2 ? 64 : 0) + bc4;

    float4 regA[4], regB[4];
    #pragma unroll
    for (int p = 0; p < 4; ++p)
        regA[p] = *(const float4*)(A + (size_t)(bm + am + p*32)*K + ak4*4);
    #pragma unroll
    for (int p = 0; p < 4; ++p)
        regB[p] = *(const float4*)(Bp + (size_t)(bk + p*8)*N + bn + bc4);
    #pragma unroll
    for (int p = 0; p < 4; ++p) {
        int m = am + p*32;
        int unit = m*8 + (ak4 ^ (m & 7));
        *(float4*)(AsF + unit*4) = to_tf32x4(regA[p]);
    }
    #pragma unroll
    for (int p = 0; p < 4; ++p)
        *(float4*)(BsF + (bk + p*8)*B_STRIDE + sOff) = to_tf32x4(regB[p]);
    __syncthreads();

    const int nIter = K / GBK;
    int buf = 0;
    for (int kt = 0; kt < nIter; ++kt) {
        bool more = (kt + 1 < nIter);
        if (more) {
            int k0 = (kt+1)*GBK;
            #pragma unroll
            for (int p = 0; p < 4; ++p)
                regA[p] = *(const float4*)(A + (size_t)(bm + am + p*32)*K + k0 + ak4*4);
            #pragma unroll
            for (int p = 0; p < 4; ++p)
                regB[p] = *(const float4*)(Bp + (size_t)(k0 + bk + p*8)*N + bn + bc4);
        }
        const unsigned aBufBase = asBase + buf*(A_BUF_F32*4);
        const float* bb = BsF + buf*B_BUF_F32;
        #pragma unroll
        for (int ks = 0; ks < 4; ++ks) {
            unsigned af[4][4];
            #pragma unroll
            for (int mt = 0; mt < 4; ++mt) {
                int m = mbase + mt*16;
                int unit = m*8 + ((ks*2 + jhi) ^ xorv);
                ldsm4(af[mt], aBufBase + unit*16);
            }
            unsigned bf1[2][2], bf2[2][2];
            #pragma unroll
            for (int nt = 0; nt < 2; ++nt) {
                bf1[nt][0] = __float_as_uint(bb[(ks*8 + kb    )*B_STRIDE + nb1 + nt*8]);
                bf1[nt][1] = __float_as_uint(bb[(ks*8 + kb + 4)*B_STRIDE + nb1 + nt*8]);
                bf2[nt][0] = __float_as_uint(bb[(ks*8 + kb    )*B_STRIDE + 64 + nb1 + nt*8]);
                bf2[nt][1] = __float_as_uint(bb[(ks*8 + kb + 4)*B_STRIDE + 64 + nb1 + nt*8]);
            }
            #pragma unroll
            for (int mt = 0; mt < 4; ++mt)
                #pragma unroll
                for (int nt = 0; nt < 2; ++nt) {
                    mma_tf32(acc1[mt][nt], af[mt], bf1[nt]);
                    mma_tf32(acc2[mt][nt], af[mt], bf2[nt]);
                }
        }
        if (more) {
            int nb = buf ^ 1;
            float* AsW = AsF + nb*A_BUF_F32;
            float* BsW = BsF + nb*B_BUF_F32;
            #pragma unroll
            for (int p = 0; p < 4; ++p) {
                int m = am + p*32;
                int unit = m*8 + (ak4 ^ (m & 7));
                *(float4*)(AsW + unit*4) = to_tf32x4(regA[p]);
            }
            #pragma unroll
            for (int p = 0; p < 4; ++p)
                *(float4*)(BsW + (bk + p*8)*B_STRIDE + sOff) = to_tf32x4(regB[p]);
        }
        __syncthreads();
        buf ^= 1;
    }

    const int gr = lane >> 2, gc = (lane & 3) * 2;
    #pragma unroll
    for (int nt = 0; nt < 2; ++nt) {
        int col = bn + warpN*16 + nt*8 + gc;
        #pragma unroll
        for (int mt = 0; mt < 4; ++mt) {
            int row = bm + warpM*64 + mt*16 + gr;
            float g0 = silu(acc1[mt][nt][0]) * acc2[mt][nt][0];
            float g1 = silu(acc1[mt][nt][1]) * acc2[mt][nt][1];
            float g2 = silu(acc1[mt][nt][2]) * acc2[mt][nt][2];
            float g3 = silu(acc1[mt][nt][3]) * acc2[mt][nt][3];
            *(float2*)(C + (size_t)row*N + col)     = make_float2(g0, g1);
            *(float2*)(C + (size_t)(row+8)*N + col) = make_float2(g2, g3);
        }
    }
}

// ---------------- attention stage 1: scores S[bh,i,t] = (q_i . k_t)/8 ----------------
#define SST 68
__global__ __launch_bounds__(256) void scores_kernel(
    const float* __restrict__ qb, const float* __restrict__ kvb, float* __restrict__ scb)
{
    extern __shared__ float smem[];
    float* sQ = smem;
    float* sK = smem + 128*SST;
    const int tid = threadIdx.x, lane = tid & 31, wid = tid >> 5;
    const int bh = blockIdx.z, b = bh >> 3, h = bh & 7;
    const int i0 = blockIdx.y * 128, t0 = blockIdx.x * 128;

    #pragma unroll
    for (int p = 0; p < 8; ++p) {
        int idx = tid + p*256;
        int row = idx >> 4, c4 = (idx & 15) << 2;
        *(float4*)(sQ + row*SST + c4) =
            to_tf32x4(*(const float4*)(qb + (size_t)(b*SEQ + i0 + row)*DMODEL + h*DHD + c4));
    }
    #pragma unroll
    for (int p = 0; p < 8; ++p) {
        int idx = tid + p*256;
        int row = idx >> 4, c4 = (idx & 15) << 2;
        *(float4*)(sK + row*SST + c4) =
            to_tf32x4(*(const float4*)(kvb + (size_t)(b*SEQ + t0 + row)*(2*DMODEL) + h*DHD + c4));
    }
    __syncthreads();

    const int warpM = wid & 1, warpN = wid >> 1;
    const int g = lane >> 2, fb = lane & 3;

    float acc[4][4][4];
    #pragma unroll
    for (int mt = 0; mt < 4; ++mt)
        #pragma unroll
        for (int nt = 0; nt < 4; ++nt)
            #pragma unroll
            for (int i = 0; i < 4; ++i) acc[mt][nt][i] = 0.0f;

    #pragma unroll
    for (int ks = 0; ks < 8; ++ks) {
        unsigned af[4][4], bf[4][2];
        #pragma unroll
        for (int mt = 0; mt < 4; ++mt) {
            const float* ap = sQ + (warpM*64 + mt*16 + g)*SST + ks*8 + fb;
            af[mt][0] = __float_as_uint(ap[0]);
            af[mt][1] = __float_as_uint(ap[8*SST]);
            af[mt][2] = __float_as_uint(ap[4]);
            af[mt][3] = __float_as_uint(ap[8*SST + 4]);
        }
        #pragma unroll
        for (int nt = 0; nt < 4; ++nt) {
            const float* bp = sK + (warpN*32 + nt*8 + g)*SST + ks*8 + fb;
            bf[nt][0] = __float_as_uint(bp[0]);
            bf[nt][1] = __float_as_uint(bp[4]);
        }
        #pragma unroll
        for (int mt = 0; mt < 4; ++mt)
            #pragma unroll
            for (int nt = 0; nt < 4; ++nt)
                mma_tf32(acc[mt][nt], af[mt], bf[nt]);
    }

    #pragma unroll
    for (int mt = 0; mt < 4; ++mt) {
        int iLo = i0 + warpM*64 + mt*16 + g;
        #pragma unroll
        for (int nt = 0; nt < 4; ++nt) {
            int t = t0 + warpN*32 + nt*8 + 2*fb;
            *(float2*)(scb + ((size_t)bh*SEQ + iLo)*SEQ + t) =
                make_float2(acc[mt][nt][0]*0.125f, acc[mt][nt][1]*0.125f);
            *(float2*)(scb + ((size_t)bh*SEQ + iLo + 8)*SEQ + t) =
                make_float2(acc[mt][nt][2]*0.125f, acc[mt][nt][3]*0.125f);
        }
    }
}

// ---------------- attention stage 2: softmax + top-512 + coef rewrite ----------------
__global__ __launch_bounds__(256, 4) void select_kernel(
    float* __restrict__ scb, float* __restrict__ sinvb)
{
    __shared__ unsigned skeys[8][1024];
    __shared__ int hist[8*256];
    const int tid = threadIdx.x, lane = tid & 31, wid = tid >> 5;
    const int r = blockIdx.x*8 + wid;
    float* row = scb + (size_t)r*SEQ;
    unsigned* keys = skeys[wid];
    int* wh = hist + wid*256;

    #pragma unroll
    for (int i = 0; i < 8; ++i) wh[lane*8 + i] = 0;
    __syncwarp();
    float z1 = 0.f;
    #pragma unroll
    for (int j = 0; j < 32; ++j) {
        float s = row[j*32 + lane];
        unsigned key = f2key(s);
        keys[j*32 + lane] = key;
        z1 += __expf(s);
        unsigned digit = key >> 24;
        unsigned grp = __match_any_sync(0xffffffffu, digit);
        if (((int)__ffs(grp) - 1) == lane) wh[digit] += __popc(grp);
    }
    z1 = warpSum(z1);
    const float invZ1 = 1.0f / z1;

    const unsigned MASKS[4]  = {0u, 0xff000000u, 0xffff0000u, 0xffffff00u};
    const int      SHIFTS[4] = {24, 16, 8, 0};
    unsigned alive = 0xffffffffu;
    unsigned prefix = 0;
    int k = SEQ/2;
    #pragma unroll
    for (int pi = 0; pi < 4; ++pi) {
        const int shift = SHIFTS[pi];
        if (pi > 0) {
            const unsigned maskHi = MASKS[pi];
            #pragma unroll
            for (int i = 0; i < 8; ++i) wh[lane*8 + i] = 0;
            __syncwarp();
            unsigned msk = alive;
            int mx = warpMaxI(__popc(msk));
            for (int it = 0; it < mx; ++it) {
                unsigned digit = 0xffffffffu;
                if (msk) {
                    int j = __ffs(msk) - 1;
                    msk &= msk - 1;
                    unsigned key = keys[j*32 + lane];
                    if (((key ^ prefix) & maskHi) == 0u) digit = (key >> shift) & 255u;
                    else alive &= ~(1u << j);
                }
                unsigned grp = __match_any_sync(0xffffffffu, digit);
                if (digit != 0xffffffffu && ((int)__ffs(grp) - 1) == lane)
                    wh[digit] += __popc(grp);
            }
        }
        __syncwarp();
        int h8[8]; int vv = 0;
        #pragma unroll
        for (int i = 0; i < 8; ++i) { h8[i] = wh[lane*8 + i]; vv += h8[i]; }
        int inc = vv;
        #pragma unroll
        for (int o = 1; o < 32; o <<= 1) {
            int tt = __shfl_down_sync(0xffffffffu, inc, o);
            if (lane + o < 32) inc += tt;
        }
        int above = inc - vv;
        int sel = -1, newk = 0;
        if (above < k && inc >= k) {
            int csum = above;
            #pragma unroll
            for (int j = 7; j >= 0; --j) {
                int hc = h8[j];
                if (csum + hc >= k) { sel = lane*8 + j; newk = k - csum; break; }
                csum += hc;
            }
        }
        unsigned bal = __ballot_sync(0xffffffffu, sel >= 0);
        int srcl = __ffs(bal) - 1;
        sel = __shfl_sync(0xffffffffu, sel, srcl);
        k   = __shfl_sync(0xffffffffu, newk, srcl);
        prefix |= ((unsigned)sel) << shift;
        __syncwarp();
    }
    const unsigned tauKey = prefix;
    const int needEq = k;

    if (lane == 0) wh[0] = 0;
    __syncwarp();
    unsigned eqmask = 0;
    #pragma unroll
    for (int j = 0; j < 32; ++j) {
        if (keys[j*32 + lane] == tauKey) {
            int p = atomicAdd(&wh[0], 1);
            if (p < 255) wh[1 + p] = j*32 + lane;
            eqmask |= 1u << j;
        }
    }
    __syncwarp();
    int neq = wh[0];
    int listN = neq < 255 ? neq : 255;
    float ctau = __uint_as_float(to_tf32(__expf(__expf(key2f(tauKey)) * invZ1)));

    float z2 = 0.f;
    #pragma unroll
    for (int j = 0; j < 32; ++j) {
        unsigned key = keys[j*32 + lane];
        float coef = 1.0f;
        if (key > tauKey)
            coef = __uint_as_float(to_tf32(__expf(__expf(key2f(key)) * invZ1)));
        row[j*32 + lane] = coef;
        z2 += coef;
    }
    z2 = warpSum(z2);

    if (eqmask) {
        unsigned em = eqmask;
        while (em) {
            int j = __ffs(em) - 1;
            em &= em - 1;
            int t = j*32 + lane;
            int rank = 0;
            for (int q = 0; q < listN; ++q) rank += (wh[1 + q] < t);
            if (rank < needEq) row[t] = ctau;
        }
    }
    int keptEq = needEq < neq ? needEq : neq;
    z2 += (ctau - 1.0f) * (float)keptEq;
    if (lane == 0) sinvb[r] = 1.0f / z2;
}

// ---------------- attention stage 3: O[bh] = diag(1/Z2) * W @ V ----------------
// W (already tf32 from select) streamed via cp.async double-buffer; V via LDG+RNA prefetch.
#define AWST 68
#define AVST 72
__global__ __launch_bounds__(256) void av_kernel(
    const float* __restrict__ scb, const float* __restrict__ kvb,
    const float* __restrict__ sinvb, float* __restrict__ ob)
{
    __shared__ float sW[2][64*AWST];
    __shared__ float sV[64*AVST];
    const int tid = threadIdx.x, lane = tid & 31, wid = tid >> 5;
    const int bh = blockIdx.y, b = bh >> 3, h = bh & 7;
    const int i0 = blockIdx.x * 64;
    const int warpM = wid & 1, warpN = wid >> 1;
    const int g = lane >> 2, fb = lane & 3;

    const unsigned swBase = (unsigned)__cvta_generic_to_shared(&sW[0][0]);
    const unsigned swStage = 64*AWST*4;

    // W cp.async mapping: 4 x 16B per thread per chunk
    const int wRow = tid >> 2, wC16 = (tid & 3) << 2;   // rows 0..63, col16 0..3 -> 4 passes? no:
    // 64 rows x 16 chunks of 16B = 1024 ops / 256 thr = 4 ops; op p: idx = tid + p*256
    // V register prefetch mapping (16 rows per pass, 4 passes)
    const int ldRow = tid >> 4, ldC4 = (tid & 15) << 2;

    float acc[2][2][4];
    #pragma unroll
    for (int mt = 0; mt < 2; ++mt)
        #pragma unroll
        for (int nt = 0; nt < 2; ++nt)
            #pragma unroll
            for (int i = 0; i < 4; ++i) acc[mt][nt][i] = 0.0f;

    // prologue: async-load W chunk 0 into stage 0; prefetch V chunk 0 into regs
    #pragma unroll
    for (int p = 0; p < 4; ++p) {
        int idx = tid + p*256;
        int row = idx >> 4, c16 = idx & 15;
        cp_async16(swBase + (unsigned)(row*AWST + c16*4)*4,
                   scb + ((size_t)bh*SEQ + i0 + row)*SEQ + c16*4);
    }
    cp_commit();
    float4 pV[4];
    #pragma unroll
    for (int p = 0; p < 4; ++p) {
        int rowi = ldRow + p*16;
        pV[p] = to_tf32x4(*(const float4*)(kvb + (size_t)(b*SEQ + rowi)*(2*DMODEL) + DMODEL + h*DHD + ldC4));
    }

    const int NC = SEQ/64;
    for (int c = 0; c < NC; ++c) {
        int buf = c & 1;
        if (c + 1 < NC) {
            int nb = buf ^ 1;
            #pragma unroll
            for (int p = 0; p < 4; ++p) {
                int idx = tid + p*256;
                int row = idx >> 4, c16 = idx & 15;
                cp_async16(swBase + nb*swStage + (unsigned)(row*AWST + c16*4)*4,
                           scb + ((size_t)bh*SEQ + i0 + row)*SEQ + (c+1)*64 + c16*4);
            }
            cp_commit();
        }
        // stage V regs -> smem
        #pragma unroll
        for (int p = 0; p < 4; ++p) {
            int rowi = ldRow + p*16;
            *(float4*)(sV + rowi*AVST + ldC4) = pV[p];
        }
        // wait for W chunk c (keep at most the newly issued group in flight)
        if (c + 1 < NC) cp_wait<1>(); else cp_wait<0>();
        __syncthreads();
        // prefetch next V into regs
        if (c + 1 < NC) {
            #pragma unroll
            for (int p = 0; p < 4; ++p) {
                int rowi = ldRow + p*16;
                pV[p] = to_tf32x4(*(const float4*)(kvb + (size_t)(b*SEQ + (c+1)*64 + rowi)*(2*DMODEL) + DMODEL + h*DHD + ldC4));
            }
        }

        const float* wb = sW[buf];
        #pragma unroll
        for (int ks = 0; ks < 8; ++ks) {
            unsigned af[2][4], bf[2][2];
            #pragma unroll
            for (int mt = 0; mt < 2; ++mt) {
                const float* ap = wb + (warpM*32 + mt*16 + g)*AWST + ks*8 + fb;
                af[mt][0] = __float_as_uint(ap[0]);
                af[mt][1] = __float_as_uint(ap[8*AWST]);
                af[mt][2] = __float_as_uint(ap[4]);
                af[mt][3] = __float_as_uint(ap[8*AWST + 4]);
            }
            #pragma unroll
            for (int nt = 0; nt < 2; ++nt) {
                const float* bp = sV + (ks*8 + fb)*AVST + warpN*16 + nt*8 + g;
                bf[nt][0] = __float_as_uint(bp[0]);
                bf[nt][1] = __float_as_uint(bp[4*AVST]);
            }
            #pragma unroll
            for (int mt = 0; mt < 2; ++mt)
                #pragma unroll
                for (int nt = 0; nt < 2; ++nt)
                    mma_tf32(acc[mt][nt], af[mt], bf[nt]);
        }
        __syncthreads();
    }

    #pragma unroll
    for (int mt = 0; mt < 2; ++mt) {
        int iLo = i0 + warpM*32 + mt*16 + g;
        int iHi = iLo + 8;
        float zLo = sinvb[bh*SEQ + iLo];
        float zHi = sinvb[bh*SEQ + iHi];
        #pragma unroll
        for (int nt = 0; nt < 2; ++nt) {
            int col = h*DHD + warpN*16 + nt*8 + 2*fb;
            *(float2*)(ob + (size_t)(b*SEQ + iLo)*DMODEL + col) =
                make_float2(acc[mt][nt][0]*zLo, acc[mt][nt][1]*zLo);
            *(float2*)(ob + (size_t)(b*SEQ + iHi)*DMODEL + col) =
                make_float2(acc[mt][nt][2]*zHi, acc[mt][nt][3]*zHi);
        }
    }
}

// ---------------- residual + RMSNorm ----------------
__global__ __launch_bounds__(128) void rms_add_kernel(
    const float* __restrict__ x, const float* __restrict__ a,
    const float* __restrict__ w, float* __restrict__ out)
{
    __shared__ float red[4];
    int row = blockIdx.x;
    int t = threadIdx.x;
    const float4* x4 = (const float4*)(x + (size_t)row*DMODEL);
    const float4* a4 = (const float4*)(a + (size_t)row*DMODEL);
    float4 xv = x4[t], av = a4[t];
    float4 s = make_float4(xv.x+av.x, xv.y+av.y, xv.z+av.z, xv.w+av.w);
    float ss = s.x*s.x + s.y*s.y + s.z*s.z + s.w*s.w;
    ss = warpSum(ss);
    if ((t & 31) == 0) red[t >> 5] = ss;
    __syncthreads();
    float tot = red[0] + red[1] + red[2] + red[3];
    float inv = rsqrtf(tot * (1.0f/DMODEL) + 1e-6f);
    float4 wv = ((const float4*)w)[t];
    ((float4*)(out + (size_t)row*DMODEL))[t] =
        make_float4(s.x*inv*wv.x, s.y*inv*wv.y, s.z*inv*wv.z, s.w*inv*wv.w);
}

// ---------------- instance norm over sequence dim ----------------
__global__ __launch_bounds__(256) void in1_kernel(
    const float* __restrict__ hh, const float* __restrict__ ffn,
    float* __restrict__ psum, float* __restrict__ psq)
{
    int b = blockIdx.y, chunk = blockIdx.x;
    int s0 = chunk * 32;
    int t = threadIdx.x;
    float s_[2] = {0.f, 0.f}, q_[2] = {0.f, 0.f};
    for (int s = 0; s < 32; ++s) {
        size_t base = ((size_t)(b*SEQ + s0 + s))*DMODEL;
        #pragma unroll
        for (int u = 0; u < 2; ++u) {
            int d = t + u*256;
            float yv = hh[base + d] + ffn[base + d];
            s_[u] += yv; q_[u] += yv*yv;
        }
    }
    #pragma unroll
    for (int u = 0; u < 2; ++u) {
        size_t pidx = ((size_t)b*32 + chunk)*DMODEL + t + u*256;
        psum[pidx] = s_[u];
        psq [pidx] = q_[u];
    }
}

__global__ void in2_kernel(const float* __restrict__ psum, const float* __restrict__ psq,
                           float* __restrict__ mean, float* __restrict__ rstd)
{
    int b = blockIdx.x, d = threadIdx.x;
    float s = 0.f, q = 0.f;
    for (int c = 0; c < 32; ++c) {
        size_t pidx = ((size_t)b*32 + c)*DMODEL + d;
        s += psum[pidx]; q += psq[pidx];
    }
    float m = s * (1.0f/SEQ);
    float v = q * (1.0f/SEQ) - m*m;
    mean[b*DMODEL + d] = m;
    rstd[b*DMODEL + d] = rsqrtf(v + 1e-5f);
}

__global__ void in3_kernel(const float* __restrict__ hh, const float* __restrict__ ffn,
                           const float* __restrict__ mean, const float* __restrict__ rstd,
                           const float* __restrict__ w, const float* __restrict__ bb,
                           float* __restrict__ out)
{
    int i = blockIdx.x*blockDim.x + threadIdx.x;
    if (i < MTOT*DMODEL) {
        int d = i & (DMODEL - 1);
        int b = i >> 19;
        float m = mean[b*DMODEL + d], r = rstd[b*DMODEL + d];
        float yv = hh[i] + ffn[i];
        out[i] = (yv - m) * r * w[d] + bb[d];
    }
}

// ---------------- launch ----------------
extern "C" void kernel_launch(void* const* d_in, const int* in_sizes, int n_in,
                              void* d_out, int out_size)
{
    (void)in_sizes; (void)n_in; (void)out_size;
    const float* x    = (const float*)d_in[0];
    const float* Wq   = (const float*)d_in[1];
    const float* bq   = (const float*)d_in[2];
    const float* Wkv  = (const float*)d_in[3];
    const float* bkv  = (const float*)d_in[4];
    const float* Wo   = (const float*)d_in[5];
    const float* bo   = (const float*)d_in[6];
    const float* rmsw = (const float*)d_in[7];
    const float* l1   = (const float*)d_in[8];
    const float* l2   = (const float*)d_in[9];
    const float* l3   = (const float*)d_in[10];
    const float* inw  = (const float*)d_in[11];
    const float* inb  = (const float*)d_in[12];
    float* out = (float*)d_out;

    float *q, *kv, *o, *att, *hbuf, *gate, *ffn, *ps, *pq, *mn, *rs, *sc, *sv;
    cudaGetSymbolAddress((void**)&q,    g_q);
    cudaGetSymbolAddress((void**)&kv,   g_kv);
    cudaGetSymbolAddress((void**)&o,    g_o);
    cudaGetSymbolAddress((void**)&att,  g_att);
    cudaGetSymbolAddress((void**)&hbuf, g_h);
    cudaGetSymbolAddress((void**)&gate, g_gate);
    cudaGetSymbolAddress((void**)&ffn,  g_ffn);
    cudaGetSymbolAddress((void**)&ps,   g_psum);
    cudaGetSymbolAddress((void**)&pq,   g_psq);
    cudaGetSymbolAddress((void**)&mn,   g_mean);
    cudaGetSymbolAddress((void**)&rs,   g_rstd);
    cudaGetSymbolAddress((void**)&sc,   g_sc);
    cudaGetSymbolAddress((void**)&sv,   g_sinv);

    const int gemmSmem = (2*A_BUF_F32 + 2*B_BUF_F32) * 4;   // 67584 B
    cudaFuncSetAttribute(tf32gemm_kernel,   cudaFuncAttributeMaxDynamicSharedMemorySize, gemmSmem);
    cudaFuncSetAttribute(qkv_gemm_kernel,   cudaFuncAttributeMaxDynamicSharedMemorySize, gemmSmem);
    cudaFuncSetAttribute(ffn12_gemm_kernel, cudaFuncAttributeMaxDynamicSharedMemorySize, gemmSmem);
    const int scoresSmem = 2*128*SST*4;                      // 69632 B
    cudaFuncSetAttribute(scores_kernel, cudaFuncAttributeMaxDynamicSharedMemorySize, scoresSmem);

    // fused QKV projection (virtual N = 1536 -> 384 blocks)
    qkv_gemm_kernel<<<dim3(3*DMODEL/128, MTOT/128), 256, gemmSmem>>>(x, Wq, bq, Wkv, bkv, q, kv);

    // sparse attention: scores -> select -> AV
    scores_kernel<<<dim3(SEQ/128, SEQ/128, BSZ*NH), 256, scoresSmem>>>(q, kv, sc);
    select_kernel<<<BSZ*NH*SEQ/8, 256>>>(sc, sv);
    av_kernel<<<dim3(SEQ/64, BSZ*NH), 256>>>(sc, kv, sv, o);

    // output projection + residual + rmsnorm
    tf32gemm_kernel<<<dim3(DMODEL/128, MTOT/128), 256, gemmSmem>>>(o, Wo, bo, att, MTOT, DMODEL, DMODEL);
    rms_add_kernel<<<MTOT, 128>>>(x, att, rmsw, hbuf);

    // SwiGLU FFN: gate = silu(h@l1) * (h@l2) in ONE launch; then l3
    ffn12_gemm_kernel<<<dim3(INNER_DIM/64, MTOT/128), 256, gemmSmem>>>(hbuf, l1, l2, gate);
    tf32gemm_kernel<<<dim3(DMODEL/128, MTOT/128), 256, gemmSmem>>>(gate, l3, nullptr, ffn, MTOT, DMODEL, INNER_DIM);

    // instance norm over sequence
    in1_kernel<<<dim3(32, BSZ), 256>>>(hbuf, ffn, ps, pq);
    in2_kernel<<<BSZ, DMODEL>>>(ps, pq, mn, rs);
    in3_kernel<<<(MTOT*DMODEL + 255)/256, 256>>>(hbuf, ffn, mn, rs, inw, inb, out);
}

// round 17
// speedup vs baseline: 1.1212x; 1.0110x over previous
#include <cuda_runtime.h>
#include <math.h>

#define BSZ 4
#define SEQ 1024
#define DMODEL 512
#define NH 8
#define DHD 64
#define INNER_DIM 1536
#define MTOT (BSZ*SEQ)   /* 4096 */

// ---------------- scratch (device globals; no runtime allocation) ----------------
__device__ float g_q   [MTOT*DMODEL];
__device__ float g_kv  [MTOT*2*DMODEL];
__device__ float g_o   [MTOT*DMODEL];
__device__ float g_att [MTOT*DMODEL];
__device__ float g_h   [MTOT*DMODEL];
__device__ float g_gate[MTOT*INNER_DIM];
__device__ float g_ffn [MTOT*DMODEL];
__device__ float g_psum[BSZ*32*DMODEL];
__device__ float g_psq [BSZ*32*DMODEL];
__device__ float g_mean[BSZ*DMODEL];
__device__ float g_rstd[BSZ*DMODEL];
__device__ float g_sc  [(size_t)BSZ*NH*SEQ*SEQ];   /* 134MB score/coef matrix */
__device__ float g_sinv[BSZ*NH*SEQ];

// ---------------- helpers ----------------
__device__ __forceinline__ unsigned f2key(float f) {
    unsigned u = __float_as_uint(f);
    return (u & 0x80000000u) ? ~u : (u | 0x80000000u);
}
__device__ __forceinline__ float key2f(unsigned k) {
    unsigned u = (k & 0x80000000u) ? (k & 0x7fffffffu) : ~k;
    return __uint_as_float(u);
}
__device__ __forceinline__ int warpMaxI(int v) {
    #pragma unroll
    for (int o = 16; o; o >>= 1) v = max(v, __shfl_xor_sync(0xffffffffu, v, o));
    return v;
}
__device__ __forceinline__ float warpSum(float v) {
    #pragma unroll
    for (int o = 16; o; o >>= 1) v += __shfl_xor_sync(0xffffffffu, v, o);
    return v;
}
__device__ __forceinline__ unsigned to_tf32(float x) {
    unsigned u;
    asm("cvt.rna.tf32.f32 %0, %1;" : "=r"(u) : "f"(x));
    return u;
}
__device__ __forceinline__ float to_tf32f(float x) { return __uint_as_float(to_tf32(x)); }
__device__ __forceinline__ float4 to_tf32x4(float4 v) {
    float4 r;
    r.x = __uint_as_float(to_tf32(v.x));
    r.y = __uint_as_float(to_tf32(v.y));
    r.z = __uint_as_float(to_tf32(v.z));
    r.w = __uint_as_float(to_tf32(v.w));
    return r;
}
__device__ __forceinline__ void ldsm4(unsigned* r, unsigned saddr) {
    asm volatile("ldmatrix.sync.aligned.m8n8.x4.shared.b16 {%0,%1,%2,%3}, [%4];"
                 : "=r"(r[0]), "=r"(r[1]), "=r"(r[2]), "=r"(r[3]) : "r"(saddr));
}
__device__ __forceinline__ void mma_tf32(float* d, const unsigned* a, const unsigned* b) {
    asm volatile(
        "mma.sync.aligned.m16n8k8.row.col.f32.tf32.tf32.f32 "
        "{%0,%1,%2,%3}, {%4,%5,%6,%7}, {%8,%9}, {%0,%1,%2,%3};"
        : "+f"(d[0]), "+f"(d[1]), "+f"(d[2]), "+f"(d[3])
        : "r"(a[0]), "r"(a[1]), "r"(a[2]), "r"(a[3]), "r"(b[0]), "r"(b[1]));
}
__device__ __forceinline__ float silu(float x) { return x / (1.f + __expf(-x)); }
__device__ __forceinline__ void cp_async16(unsigned saddr, const void* gaddr) {
    asm volatile("cp.async.cg.shared.global [%0], [%1], 16;" :: "r"(saddr), "l"(gaddr));
}
__device__ __forceinline__ void cp_commit() {
    asm volatile("cp.async.commit_group;");
}
template<int N>
__device__ __forceinline__ void cp_wait() {
    asm volatile("cp.async.wait_group %0;" :: "n"(N));
}

#define GBK 32
#define A_BUF_F32 4096           /* 128*32 */
#define B_STRIDE 136             /* 128 + 8 pad */
#define B_BUF_F32 (GBK*B_STRIDE) /* 4352 */

// ---------------- generic TF32 GEMM: C[M,N] = A[M,K] @ B[K,N] (+bias) ----------------
__global__ __launch_bounds__(256, 2) void tf32gemm_kernel(
    const float* __restrict__ A, const float* __restrict__ B,
    const float* __restrict__ bias, float* __restrict__ C,
    int M, int N, int K)
{
    extern __shared__ float gsm[];
    float* AsF = gsm;
    float* BsF = gsm + 2*A_BUF_F32;
    const unsigned asBase = (unsigned)__cvta_generic_to_shared(AsF);

    const int tid = threadIdx.x, lane = tid & 31, wid = tid >> 5;
    const int warpM = wid & 1, warpN = wid >> 1;
    const int bm = blockIdx.y * 128, bn = blockIdx.x * 128;

    const int mbase = warpM*64 + ((lane>>3)&1)*8 + (lane&7);
    const int jhi   = lane >> 4;
    const int xorv  = lane & 7;
    const int kb    = lane & 3;
    const int nbase = warpN*32 + (lane>>2);

    float acc[4][4][4];
    #pragma unroll
    for (int mt = 0; mt < 4; ++mt)
        #pragma unroll
        for (int nt = 0; nt < 4; ++nt)
            #pragma unroll
            for (int i = 0; i < 4; ++i) acc[mt][nt][i] = 0.0f;

    const int am = tid >> 3, ak4 = tid & 7;
    const int bk = tid >> 5, bn4 = tid & 31;

    float4 regA[4], regB[4];
    #pragma unroll
    for (int p = 0; p < 4; ++p)
        regA[p] = *(const float4*)(A + (size_t)(bm + am + p*32)*K + ak4*4);
    #pragma unroll
    for (int p = 0; p < 4; ++p)
        regB[p] = *(const float4*)(B + (size_t)(bk + p*8)*N + bn + bn4*4);
    #pragma unroll
    for (int p = 0; p < 4; ++p) {
        int m = am + p*32;
        int unit = m*8 + (ak4 ^ (m & 7));
        *(float4*)(AsF + unit*4) = to_tf32x4(regA[p]);
    }
    #pragma unroll
    for (int p = 0; p < 4; ++p)
        *(float4*)(BsF + (bk + p*8)*B_STRIDE + bn4*4) = to_tf32x4(regB[p]);
    __syncthreads();

    const int nIter = K / GBK;
    int buf = 0;
    for (int kt = 0; kt < nIter; ++kt) {
        bool more = (kt + 1 < nIter);
        if (more) {
            int k0 = (kt+1)*GBK;
            #pragma unroll
            for (int p = 0; p < 4; ++p)
                regA[p] = *(const float4*)(A + (size_t)(bm + am + p*32)*K + k0 + ak4*4);
            #pragma unroll
            for (int p = 0; p < 4; ++p)
                regB[p] = *(const float4*)(B + (size_t)(k0 + bk + p*8)*N + bn + bn4*4);
        }
        const unsigned aBufBase = asBase + buf*(A_BUF_F32*4);
        const float* bb = BsF + buf*B_BUF_F32;
        #pragma unroll
        for (int ks = 0; ks < 4; ++ks) {
            unsigned af[4][4];
            #pragma unroll
            for (int mt = 0; mt < 4; ++mt) {
                int m = mbase + mt*16;
                int unit = m*8 + ((ks*2 + jhi) ^ xorv);
                ldsm4(af[mt], aBufBase + unit*16);
            }
            unsigned bf[4][2];
            #pragma unroll
            for (int nt = 0; nt < 4; ++nt) {
                bf[nt][0] = __float_as_uint(bb[(ks*8 + kb    )*B_STRIDE + nbase + nt*8]);
                bf[nt][1] = __float_as_uint(bb[(ks*8 + kb + 4)*B_STRIDE + nbase + nt*8]);
            }
            #pragma unroll
            for (int mt = 0; mt < 4; ++mt)
                #pragma unroll
                for (int nt = 0; nt < 4; ++nt)
                    mma_tf32(acc[mt][nt], af[mt], bf[nt]);
        }
        if (more) {
            int nb = buf ^ 1;
            float* AsW = AsF + nb*A_BUF_F32;
            float* BsW = BsF + nb*B_BUF_F32;
            #pragma unroll
            for (int p = 0; p < 4; ++p) {
                int m = am + p*32;
                int unit = m*8 + (ak4 ^ (m & 7));
                *(float4*)(AsW + unit*4) = to_tf32x4(regA[p]);
            }
            #pragma unroll
            for (int p = 0; p < 4; ++p)
                *(float4*)(BsW + (bk + p*8)*B_STRIDE + bn4*4) = to_tf32x4(regB[p]);
        }
        __syncthreads();
        buf ^= 1;
    }

    const int gr = lane >> 2, gc = (lane & 3) * 2;
    #pragma unroll
    for (int nt = 0; nt < 4; ++nt) {
        int col = bn + warpN*32 + nt*8 + gc;
        float b0v = bias ? bias[col]   : 0.0f;
        float b1v = bias ? bias[col+1] : 0.0f;
        #pragma unroll
        for (int mt = 0; mt < 4; ++mt) {
            int row = bm + warpM*64 + mt*16 + gr;
            *(float2*)(C + (size_t)row*N + col)     = make_float2(acc[mt][nt][0]+b0v, acc[mt][nt][1]+b1v);
            *(float2*)(C + (size_t)(row+8)*N + col) = make_float2(acc[mt][nt][2]+b0v, acc[mt][nt][3]+b1v);
        }
    }
}

// ---------------- fused QKV GEMM: virtual N=1536 over {Wq->q, Wkv->kv} ----------------
// Epilogue writes RNA-tf32-rounded values (identity under downstream re-rounding).
__global__ __launch_bounds__(256, 2) void qkv_gemm_kernel(
    const float* __restrict__ A,
    const float* __restrict__ Wq, const float* __restrict__ bq,
    const float* __restrict__ Wkv, const float* __restrict__ bkv,
    float* __restrict__ Q, float* __restrict__ KV)
{
    extern __shared__ float gsm[];
    float* AsF = gsm;
    float* BsF = gsm + 2*A_BUF_F32;
    const unsigned asBase = (unsigned)__cvta_generic_to_shared(AsF);

    const int tid = threadIdx.x, lane = tid & 31, wid = tid >> 5;
    const int warpM = wid & 1, warpN = wid >> 1;
    const int bm = blockIdx.y * 128;
    const int bnv = blockIdx.x * 128;

    const float* B;
    const float* bias;
    float* C;
    int Nr, cb;
    if (bnv < DMODEL) { B = Wq;  bias = bq;  C = Q;  Nr = DMODEL;   cb = bnv; }
    else              { B = Wkv; bias = bkv; C = KV; Nr = 2*DMODEL; cb = bnv - DMODEL; }

    const int K = DMODEL;
    const int mbase = warpM*64 + ((lane>>3)&1)*8 + (lane&7);
    const int jhi   = lane >> 4;
    const int xorv  = lane & 7;
    const int kb    = lane & 3;
    const int nbase = warpN*32 + (lane>>2);

    float acc[4][4][4];
    #pragma unroll
    for (int mt = 0; mt < 4; ++mt)
        #pragma unroll
        for (int nt = 0; nt < 4; ++nt)
            #pragma unroll
            for (int i = 0; i < 4; ++i) acc[mt][nt][i] = 0.0f;

    const int am = tid >> 3, ak4 = tid & 7;
    const int bk = tid >> 5, bn4 = tid & 31;

    float4 regA[4], regB[4];
    #pragma unroll
    for (int p = 0; p < 4; ++p)
        regA[p] = *(const float4*)(A + (size_t)(bm + am + p*32)*K + ak4*4);
    #pragma unroll
    for (int p = 0; p < 4; ++p)
        regB[p] = *(const float4*)(B + (size_t)(bk + p*8)*Nr + cb + bn4*4);
    #pragma unroll
    for (int p = 0; p < 4; ++p) {
        int m = am + p*32;
        int unit = m*8 + (ak4 ^ (m & 7));
        *(float4*)(AsF + unit*4) = to_tf32x4(regA[p]);
    }
    #pragma unroll
    for (int p = 0; p < 4; ++p)
        *(float4*)(BsF + (bk + p*8)*B_STRIDE + bn4*4) = to_tf32x4(regB[p]);
    __syncthreads();

    const int nIter = K / GBK;
    int buf = 0;
    for (int kt = 0; kt < nIter; ++kt) {
        bool more = (kt + 1 < nIter);
        if (more) {
            int k0 = (kt+1)*GBK;
            #pragma unroll
            for (int p = 0; p < 4; ++p)
                regA[p] = *(const float4*)(A + (size_t)(bm + am + p*32)*K + k0 + ak4*4);
            #pragma unroll
            for (int p = 0; p < 4; ++p)
                regB[p] = *(const float4*)(B + (size_t)(k0 + bk + p*8)*Nr + cb + bn4*4);
        }
        const unsigned aBufBase = asBase + buf*(A_BUF_F32*4);
        const float* bb = BsF + buf*B_BUF_F32;
        #pragma unroll
        for (int ks = 0; ks < 4; ++ks) {
            unsigned af[4][4];
            #pragma unroll
            for (int mt = 0; mt < 4; ++mt) {
                int m = mbase + mt*16;
                int unit = m*8 + ((ks*2 + jhi) ^ xorv);
                ldsm4(af[mt], aBufBase + unit*16);
            }
            unsigned bf[4][2];
            #pragma unroll
            for (int nt = 0; nt < 4; ++nt) {
                bf[nt][0] = __float_as_uint(bb[(ks*8 + kb    )*B_STRIDE + nbase + nt*8]);
                bf[nt][1] = __float_as_uint(bb[(ks*8 + kb + 4)*B_STRIDE + nbase + nt*8]);
            }
            #pragma unroll
            for (int mt = 0; mt < 4; ++mt)
                #pragma unroll
                for (int nt = 0; nt < 4; ++nt)
                    mma_tf32(acc[mt][nt], af[mt], bf[nt]);
        }
        if (more) {
            int nb = buf ^ 1;
            float* AsW = AsF + nb*A_BUF_F32;
            float* BsW = BsF + nb*B_BUF_F32;
            #pragma unroll
            for (int p = 0; p < 4; ++p) {
                int m = am + p*32;
                int unit = m*8 + (ak4 ^ (m & 7));
                *(float4*)(AsW + unit*4) = to_tf32x4(regA[p]);
            }
            #pragma unroll
            for (int p = 0; p < 4; ++p)
                *(float4*)(BsW + (bk + p*8)*B_STRIDE + bn4*4) = to_tf32x4(regB[p]);
        }
        __syncthreads();
        buf ^= 1;
    }

    const int gr = lane >> 2, gc = (lane & 3) * 2;
    #pragma unroll
    for (int nt = 0; nt < 4; ++nt) {
        int col = cb + warpN*32 + nt*8 + gc;
        float b0v = bias[col], b1v = bias[col+1];
        #pragma unroll
        for (int mt = 0; mt < 4; ++mt) {
            int row = bm + warpM*64 + mt*16 + gr;
            *(float2*)(C + (size_t)row*Nr + col) =
                make_float2(to_tf32f(acc[mt][nt][0]+b0v), to_tf32f(acc[mt][nt][1]+b1v));
            *(float2*)(C + (size_t)(row+8)*Nr + col) =
                make_float2(to_tf32f(acc[mt][nt][2]+b0v), to_tf32f(acc[mt][nt][3]+b1v));
        }
    }
}

// ---------------- fused FFN l1+l2 GEMM: gate = silu(A@l1) * (A@l2) ----------------
__global__ __launch_bounds__(256, 2) void ffn12_gemm_kernel(
    const float* __restrict__ A, const float* __restrict__ B1,
    const float* __restrict__ B2, float* __restrict__ C)
{
    extern __shared__ float gsm[];
    float* AsF = gsm;
    float* BsF = gsm + 2*A_BUF_F32;
    const unsigned asBase = (unsigned)__cvta_generic_to_shared(AsF);

    const int tid = threadIdx.x, lane = tid & 31, wid = tid >> 5;
    const int warpM = wid & 1, warpN = wid >> 1;
    const int bm = blockIdx.y * 128, bn = blockIdx.x * 64;
    const int K = DMODEL, N = INNER_DIM;

    const int mbase = warpM*64 + ((lane>>3)&1)*8 + (lane&7);
    const int jhi   = lane >> 4;
    const int xorv  = lane & 7;
    const int kb    = lane & 3;
    const int nb1   = warpN*16 + (lane>>2);

    float acc1[4][2][4], acc2[4][2][4];
    #pragma unroll
    for (int mt = 0; mt < 4; ++mt)
        #pragma unroll
        for (int nt = 0; nt < 2; ++nt)
            #pragma unroll
            for (int i = 0; i < 4; ++i) { acc1[mt][nt][i] = 0.0f; acc2[mt][nt][i] = 0.0f; }

    const int am = tid >> 3, ak4 = tid & 7;
    const int bk = tid >> 5, bn4 = tid & 31;
    const bool isB2 = bn4 >= 16;
    const int bc4 = (bn4 & 15) * 4;
    const float* Bp = isB2 ? B2 : B1;
    const int sOff = (isB2 ? 64 : 0) + bc4;

    float4 regA[4], regB[4];
    #pragma unroll
    for (int p = 0; p < 4; ++p)
        regA[p] = *(const float4*)(A + (size_t)(bm + am + p*32)*K + ak4*4);
    #pragma unroll
    for (int p = 0; p < 4; ++p)
        regB[p] = *(const float4*)(Bp + (size_t)(bk + p*8)*N + bn + bc4);
    #pragma unroll
    for (int p = 0; p < 4; ++p) {
        int m = am + p*32;
        int unit = m*8 + (ak4 ^ (m & 7));
        *(float4*)(AsF + unit*4) = to_tf32x4(regA[p]);
    }
    #pragma unroll
    for (int p = 0; p < 4; ++p)
        *(float4*)(BsF + (bk + p*8)*B_STRIDE + sOff) = to_tf32x4(regB[p]);
    __syncthreads();

    const int nIter = K / GBK;
    int buf = 0;
    for (int kt = 0; kt < nIter; ++kt) {
        bool more = (kt + 1 < nIter);
        if (more) {
            int k0 = (kt+1)*GBK;
            #pragma unroll
            for (int p = 0; p < 4; ++p)
                regA[p] = *(const float4*)(A + (size_t)(bm + am + p*32)*K + k0 + ak4*4);
            #pragma unroll
            for (int p = 0; p < 4; ++p)
                regB[p] = *(const float4*)(Bp + (size_t)(k0 + bk + p*8)*N + bn + bc4);
        }
        const unsigned aBufBase = asBase + buf*(A_BUF_F32*4);
        const float* bb = BsF + buf*B_BUF_F32;
        #pragma unroll
        for (int ks = 0; ks < 4; ++ks) {
            unsigned af[4][4];
            #pragma unroll
            for (int mt = 0; mt < 4; ++mt) {
                int m = mbase + mt*16;
                int unit = m*8 + ((ks*2 + jhi) ^ xorv);
                ldsm4(af[mt], aBufBase + unit*16);
            }
            unsigned bf1[2][2], bf2[2][2];
            #pragma unroll
            for (int nt = 0; nt < 2; ++nt) {
                bf1[nt][0] = __float_as_uint(bb[(ks*8 + kb    )*B_STRIDE + nb1 + nt*8]);
                bf1[nt][1] = __float_as_uint(bb[(ks*8 + kb + 4)*B_STRIDE + nb1 + nt*8]);
                bf2[nt][0] = __float_as_uint(bb[(ks*8 + kb    )*B_STRIDE + 64 + nb1 + nt*8]);
                bf2[nt][1] = __float_as_uint(bb[(ks*8 + kb + 4)*B_STRIDE + 64 + nb1 + nt*8]);
            }
            #pragma unroll
            for (int mt = 0; mt < 4; ++mt)
                #pragma unroll
                for (int nt = 0; nt < 2; ++nt) {
                    mma_tf32(acc1[mt][nt], af[mt], bf1[nt]);
                    mma_tf32(acc2[mt][nt], af[mt], bf2[nt]);
                }
        }
        if (more) {
            int nb = buf ^ 1;
            float* AsW = AsF + nb*A_BUF_F32;
            float* BsW = BsF + nb*B_BUF_F32;
            #pragma unroll
            for (int p = 0; p < 4; ++p) {
                int m = am + p*32;
                int unit = m*8 + (ak4 ^ (m & 7));
                *(float4*)(AsW + unit*4) = to_tf32x4(regA[p]);
            }
            #pragma unroll
            for (int p = 0; p < 4; ++p)
                *(float4*)(BsW + (bk + p*8)*B_STRIDE + sOff) = to_tf32x4(regB[p]);
        }
        __syncthreads();
        buf ^= 1;
    }

    const int gr = lane >> 2, gc = (lane & 3) * 2;
    #pragma unroll
    for (int nt = 0; nt < 2; ++nt) {
        int col = bn + warpN*16 + nt*8 + gc;
        #pragma unroll
        for (int mt = 0; mt < 4; ++mt) {
            int row = bm + warpM*64 + mt*16 + gr;
            float g0 = silu(acc1[mt][nt][0]) * acc2[mt][nt][0];
            float g1 = silu(acc1[mt][nt][1]) * acc2[mt][nt][1];
            float g2 = silu(acc1[mt][nt][2]) * acc2[mt][nt][2];
            float g3 = silu(acc1[mt][nt][3]) * acc2[mt][nt][3];
            *(float2*)(C + (size_t)row*N + col)     = make_float2(g0, g1);
            *(float2*)(C + (size_t)(row+8)*N + col) = make_float2(g2, g3);
        }
    }
}

// ---------------- attention stage 1: scores S[bh,i,t] = (q_i . k_t)/8 ----------------
#define SST 68
__global__ __launch_bounds__(256) void scores_kernel(
    const float* __restrict__ qb, const float* __restrict__ kvb, float* __restrict__ scb)
{
    extern __shared__ float smem[];
    float* sQ = smem;
    float* sK = smem + 128*SST;
    const int tid = threadIdx.x, lane = tid & 31, wid = tid >> 5;
    const int bh = blockIdx.z, b = bh >> 3, h = bh & 7;
    const int i0 = blockIdx.y * 128, t0 = blockIdx.x * 128;

    #pragma unroll
    for (int p = 0; p < 8; ++p) {
        int idx = tid + p*256;
        int row = idx >> 4, c4 = (idx & 15) << 2;
        *(float4*)(sQ + row*SST + c4) =
            *(const float4*)(qb + (size_t)(b*SEQ + i0 + row)*DMODEL + h*DHD + c4);
    }
    #pragma unroll
    for (int p = 0; p < 8; ++p) {
        int idx = tid + p*256;
        int row = idx >> 4, c4 = (idx & 15) << 2;
        *(float4*)(sK + row*SST + c4) =
            *(const float4*)(kvb + (size_t)(b*SEQ + t0 + row)*(2*DMODEL) + h*DHD + c4);
    }
    __syncthreads();

    const int warpM = wid & 1, warpN = wid >> 1;
    const int g = lane >> 2, fb = lane & 3;

    float acc[4][4][4];
    #pragma unroll
    for (int mt = 0; mt < 4; ++mt)
        #pragma unroll
        for (int nt = 0; nt < 4; ++nt)
            #pragma unroll
            for (int i = 0; i < 4; ++i) acc[mt][nt][i] = 0.0f;

    #pragma unroll
    for (int ks = 0; ks < 8; ++ks) {
        unsigned af[4][4], bf[4][2];
        #pragma unroll
        for (int mt = 0; mt < 4; ++mt) {
            const float* ap = sQ + (warpM*64 + mt*16 + g)*SST + ks*8 + fb;
            af[mt][0] = __float_as_uint(ap[0]);
            af[mt][1] = __float_as_uint(ap[8*SST]);
            af[mt][2] = __float_as_uint(ap[4]);
            af[mt][3] = __float_as_uint(ap[8*SST + 4]);
        }
        #pragma unroll
        for (int nt = 0; nt < 4; ++nt) {
            const float* bp = sK + (warpN*32 + nt*8 + g)*SST + ks*8 + fb;
            bf[nt][0] = __float_as_uint(bp[0]);
            bf[nt][1] = __float_as_uint(bp[4]);
        }
        #pragma unroll
        for (int mt = 0; mt < 4; ++mt)
            #pragma unroll
            for (int nt = 0; nt < 4; ++nt)
                mma_tf32(acc[mt][nt], af[mt], bf[nt]);
    }

    #pragma unroll
    for (int mt = 0; mt < 4; ++mt) {
        int iLo = i0 + warpM*64 + mt*16 + g;
        #pragma unroll
        for (int nt = 0; nt < 4; ++nt) {
            int t = t0 + warpN*32 + nt*8 + 2*fb;
            *(float2*)(scb + ((size_t)bh*SEQ + iLo)*SEQ + t) =
                make_float2(acc[mt][nt][0]*0.125f, acc[mt][nt][1]*0.125f);
            *(float2*)(scb + ((size_t)bh*SEQ + iLo + 8)*SEQ + t) =
                make_float2(acc[mt][nt][2]*0.125f, acc[mt][nt][3]*0.125f);
        }
    }
}

// ---------------- attention stage 2: softmax + top-512 + coef rewrite ----------------
__global__ __launch_bounds__(256, 4) void select_kernel(
    float* __restrict__ scb, float* __restrict__ sinvb)
{
    __shared__ unsigned skeys[8][1024];
    __shared__ int hist[8*256];
    const int tid = threadIdx.x, lane = tid & 31, wid = tid >> 5;
    const int r = blockIdx.x*8 + wid;
    float* row = scb + (size_t)r*SEQ;
    unsigned* keys = skeys[wid];
    int* wh = hist + wid*256;

    #pragma unroll
    for (int i = 0; i < 8; ++i) wh[lane*8 + i] = 0;
    __syncwarp();
    float z1 = 0.f;
    #pragma unroll
    for (int j = 0; j < 32; ++j) {
        float s = row[j*32 + lane];
        unsigned key = f2key(s);
        keys[j*32 + lane] = key;
        z1 += __expf(s);
        unsigned digit = key >> 24;
        unsigned grp = __match_any_sync(0xffffffffu, digit);
        if (((int)__ffs(grp) - 1) == lane) wh[digit] += __popc(grp);
    }
    z1 = warpSum(z1);
    const float invZ1 = 1.0f / z1;

    const unsigned MASKS[4]  = {0u, 0xff000000u, 0xffff0000u, 0xffffff00u};
    const int      SHIFTS[4] = {24, 16, 8, 0};
    unsigned alive = 0xffffffffu;
    unsigned prefix = 0;
    int k = SEQ/2;
    #pragma unroll
    for (int pi = 0; pi < 4; ++pi) {
        const int shift = SHIFTS[pi];
        if (pi > 0) {
            const unsigned maskHi = MASKS[pi];
            #pragma unroll
            for (int i = 0; i < 8; ++i) wh[lane*8 + i] = 0;
            __syncwarp();
            unsigned msk = alive;
            int mx = warpMaxI(__popc(msk));
            for (int it = 0; it < mx; ++it) {
                unsigned digit = 0xffffffffu;
                if (msk) {
                    int j = __ffs(msk) - 1;
                    msk &= msk - 1;
                    unsigned key = keys[j*32 + lane];
                    if (((key ^ prefix) & maskHi) == 0u) digit = (key >> shift) & 255u;
                    else alive &= ~(1u << j);
                }
                unsigned grp = __match_any_sync(0xffffffffu, digit);
                if (digit != 0xffffffffu && ((int)__ffs(grp) - 1) == lane)
                    wh[digit] += __popc(grp);
            }
        }
        __syncwarp();
        int h8[8]; int vv = 0;
        #pragma unroll
        for (int i = 0; i < 8; ++i) { h8[i] = wh[lane*8 + i]; vv += h8[i]; }
        int inc = vv;
        #pragma unroll
        for (int o = 1; o < 32; o <<= 1) {
            int tt = __shfl_down_sync(0xffffffffu, inc, o);
            if (lane + o < 32) inc += tt;
        }
        int above = inc - vv;
        int sel = -1, newk = 0;
        if (above < k && inc >= k) {
            int csum = above;
            #pragma unroll
            for (int j = 7; j >= 0; --j) {
                int hc = h8[j];
                if (csum + hc >= k) { sel = lane*8 + j; newk = k - csum; break; }
                csum += hc;
            }
        }
        unsigned bal = __ballot_sync(0xffffffffu, sel >= 0);
        int srcl = __ffs(bal) - 1;
        sel = __shfl_sync(0xffffffffu, sel, srcl);
        k   = __shfl_sync(0xffffffffu, newk, srcl);
        prefix |= ((unsigned)sel) << shift;
        __syncwarp();
    }
    const unsigned tauKey = prefix;
    const int needEq = k;

    if (lane == 0) wh[0] = 0;
    __syncwarp();
    unsigned eqmask = 0;
    #pragma unroll
    for (int j = 0; j < 32; ++j) {
        if (keys[j*32 + lane] == tauKey) {
            int p = atomicAdd(&wh[0], 1);
            if (p < 255) wh[1 + p] = j*32 + lane;
            eqmask |= 1u << j;
        }
    }
    __syncwarp();
    int neq = wh[0];
    int listN = neq < 255 ? neq : 255;
    float ctau = __uint_as_float(to_tf32(__expf(__expf(key2f(tauKey)) * invZ1)));

    float z2 = 0.f;
    #pragma unroll
    for (int j = 0; j < 32; ++j) {
        unsigned key = keys[j*32 + lane];
        float coef = 1.0f;
        if (key > tauKey)
            coef = __uint_as_float(to_tf32(__expf(__expf(key2f(key)) * invZ1)));
        row[j*32 + lane] = coef;
        z2 += coef;
    }
    z2 = warpSum(z2);

    if (eqmask) {
        unsigned em = eqmask;
        while (em) {
            int j = __ffs(em) - 1;
            em &= em - 1;
            int t = j*32 + lane;
            int rank = 0;
            for (int q = 0; q < listN; ++q) rank += (wh[1 + q] < t);
            if (rank < needEq) row[t] = ctau;
        }
    }
    int keptEq = needEq < neq ? needEq : neq;
    z2 += (ctau - 1.0f) * (float)keptEq;
    if (lane == 0) sinvb[r] = 1.0f / z2;
}

// ---------------- attention stage 3: O[bh] = diag(1/Z2) * W @ V ----------------
// Both W (tf32 coefs) and V (tf32-rounded kv) streamed via cp.async double-buffer.
#define AWST 68
#define AVST 72
__global__ __launch_bounds__(256) void av_kernel(
    const float* __restrict__ scb, const float* __restrict__ kvb,
    const float* __restrict__ sinvb, float* __restrict__ ob)
{
    extern __shared__ float avsm[];
    float* sW = avsm;                    // 2 * 64*AWST
    float* sV = avsm + 2*64*AWST;        // 2 * 64*AVST
    const unsigned swBase = (unsigned)__cvta_generic_to_shared(sW);
    const unsigned svBase = (unsigned)__cvta_generic_to_shared(sV);
    const unsigned swStage = 64*AWST*4;
    const unsigned svStage = 64*AVST*4;

    const int tid = threadIdx.x, lane = tid & 31, wid = tid >> 5;
    const int bh = blockIdx.y, b = bh >> 3, h = bh & 7;
    const int i0 = blockIdx.x * 64;
    const int warpM = wid & 1, warpN = wid >> 1;
    const int g = lane >> 2, fb = lane & 3;

    // W/V cp.async mapping: 64 rows x 16 chunks of 16B = 1024 ops = 4/thread each
    const int ldRow = tid >> 4, ldC16 = tid & 15;

    float acc[2][2][4];
    #pragma unroll
    for (int mt = 0; mt < 2; ++mt)
        #pragma unroll
        for (int nt = 0; nt < 2; ++nt)
            #pragma unroll
            for (int i = 0; i < 4; ++i) acc[mt][nt][i] = 0.0f;

    // prologue: async-load W+V chunk 0 into stage 0
    #pragma unroll
    for (int p = 0; p < 4; ++p) {
        int row = ldRow + p*16;
        cp_async16(swBase + (unsigned)(row*AWST + ldC16*4)*4,
                   scb + ((size_t)bh*SEQ + i0 + row)*SEQ + ldC16*4);
        cp_async16(svBase + (unsigned)(row*AVST + ldC16*4)*4,
                   kvb + (size_t)(b*SEQ + row)*(2*DMODEL) + DMODEL + h*DHD + ldC16*4);
    }
    cp_commit();

    const int NC = SEQ/64;
    for (int c = 0; c < NC; ++c) {
        int buf = c & 1;
        if (c + 1 < NC) {
            int nb = buf ^ 1;
            #pragma unroll
            for (int p = 0; p < 4; ++p) {
                int row = ldRow + p*16;
                cp_async16(swBase + nb*swStage + (unsigned)(row*AWST + ldC16*4)*4,
                           scb + ((size_t)bh*SEQ + i0 + row)*SEQ + (c+1)*64 + ldC16*4);
                cp_async16(svBase + nb*svStage + (unsigned)(row*AVST + ldC16*4)*4,
                           kvb + (size_t)(b*SEQ + (c+1)*64 + row)*(2*DMODEL) + DMODEL + h*DHD + ldC16*4);
            }
            cp_commit();
            cp_wait<1>();
        } else {
            cp_wait<0>();
        }
        __syncthreads();

        const float* wb = sW + buf*(64*AWST);
        const float* vb = sV + buf*(64*AVST);
        #pragma unroll
        for (int ks = 0; ks < 8; ++ks) {
            unsigned af[2][4], bf[2][2];
            #pragma unroll
            for (int mt = 0; mt < 2; ++mt) {
                const float* ap = wb + (warpM*32 + mt*16 + g)*AWST + ks*8 + fb;
                af[mt][0] = __float_as_uint(ap[0]);
                af[mt][1] = __float_as_uint(ap[8*AWST]);
                af[mt][2] = __float_as_uint(ap[4]);
                af[mt][3] = __float_as_uint(ap[8*AWST + 4]);
            }
            #pragma unroll
            for (int nt = 0; nt < 2; ++nt) {
                const float* bp = vb + (ks*8 + fb)*AVST + warpN*16 + nt*8 + g;
                bf[nt][0] = __float_as_uint(bp[0]);
                bf[nt][1] = __float_as_uint(bp[4*AVST]);
            }
            #pragma unroll
            for (int mt = 0; mt < 2; ++mt)
                #pragma unroll
                for (int nt = 0; nt < 2; ++nt)
                    mma_tf32(acc[mt][nt], af[mt], bf[nt]);
        }
        __syncthreads();
    }

    #pragma unroll
    for (int mt = 0; mt < 2; ++mt) {
        int iLo = i0 + warpM*32 + mt*16 + g;
        int iHi = iLo + 8;
        float zLo = sinvb[bh*SEQ + iLo];
        float zHi = sinvb[bh*SEQ + iHi];
        #pragma unroll
        for (int nt = 0; nt < 2; ++nt) {
            int col = h*DHD + warpN*16 + nt*8 + 2*fb;
            *(float2*)(ob + (size_t)(b*SEQ + iLo)*DMODEL + col) =
                make_float2(acc[mt][nt][0]*zLo, acc[mt][nt][1]*zLo);
            *(float2*)(ob + (size_t)(b*SEQ + iHi)*DMODEL + col) =
                make_float2(acc[mt][nt][2]*zHi, acc[mt][nt][3]*zHi);
        }
    }
}

// ---------------- residual + RMSNorm ----------------
__global__ __launch_bounds__(128) void rms_add_kernel(
    const float* __restrict__ x, const float* __restrict__ a,
    const float* __restrict__ w, float* __restrict__ out)
{
    __shared__ float red[4];
    int row = blockIdx.x;
    int t = threadIdx.x;
    const float4* x4 = (const float4*)(x + (size_t)row*DMODEL);
    const float4* a4 = (const float4*)(a + (size_t)row*DMODEL);
    float4 xv = x4[t], av = a4[t];
    float4 s = make_float4(xv.x+av.x, xv.y+av.y, xv.z+av.z, xv.w+av.w);
    float ss = s.x*s.x + s.y*s.y + s.z*s.z + s.w*s.w;
    ss = warpSum(ss);
    if ((t & 31) == 0) red[t >> 5] = ss;
    __syncthreads();
    float tot = red[0] + red[1] + red[2] + red[3];
    float inv = rsqrtf(tot * (1.0f/DMODEL) + 1e-6f);
    float4 wv = ((const float4*)w)[t];
    ((float4*)(out + (size_t)row*DMODEL))[t] =
        make_float4(s.x*inv*wv.x, s.y*inv*wv.y, s.z*inv*wv.z, s.w*inv*wv.w);
}

// ---------------- instance norm over sequence dim ----------------
__global__ __launch_bounds__(256) void in1_kernel(
    const float* __restrict__ hh, const float* __restrict__ ffn,
    float* __restrict__ psum, float* __restrict__ psq)
{
    int b = blockIdx.y, chunk = blockIdx.x;
    int s0 = chunk * 32;
    int t = threadIdx.x;
    float s_[2] = {0.f, 0.f}, q_[2] = {0.f, 0.f};
    for (int s = 0; s < 32; ++s) {
        size_t base = ((size_t)(b*SEQ + s0 + s))*DMODEL;
        #pragma unroll
        for (int u = 0; u < 2; ++u) {
            int d = t + u*256;
            float yv = hh[base + d] + ffn[base + d];
            s_[u] += yv; q_[u] += yv*yv;
        }
    }
    #pragma unroll
    for (int u = 0; u < 2; ++u) {
        size_t pidx = ((size_t)b*32 + chunk)*DMODEL + t + u*256;
        psum[pidx] = s_[u];
        psq [pidx] = q_[u];
    }
}

__global__ void in2_kernel(const float* __restrict__ psum, const float* __restrict__ psq,
                           float* __restrict__ mean, float* __restrict__ rstd)
{
    int b = blockIdx.x, d = threadIdx.x;
    float s = 0.f, q = 0.f;
    for (int c = 0; c < 32; ++c) {
        size_t pidx = ((size_t)b*32 + c)*DMODEL + d;
        s += psum[pidx]; q += psq[pidx];
    }
    float m = s * (1.0f/SEQ);
    float v = q * (1.0f/SEQ) - m*m;
    mean[b*DMODEL + d] = m;
    rstd[b*DMODEL + d] = rsqrtf(v + 1e-5f);
}

__global__ void in3_kernel(const float* __restrict__ hh, const float* __restrict__ ffn,
                           const float* __restrict__ mean, const float* __restrict__ rstd,
                           const float* __restrict__ w, const float* __restrict__ bb,
                           float* __restrict__ out)
{
    int i = blockIdx.x*blockDim.x + threadIdx.x;
    if (i < MTOT*DMODEL) {
        int d = i & (DMODEL - 1);
        int b = i >> 19;
        float m = mean[b*DMODEL + d], r = rstd[b*DMODEL + d];
        float yv = hh[i] + ffn[i];
        out[i] = (yv - m) * r * w[d] + bb[d];
    }
}

// ---------------- launch ----------------
extern "C" void kernel_launch(void* const* d_in, const int* in_sizes, int n_in,
                              void* d_out, int out_size)
{
    (void)in_sizes; (void)n_in; (void)out_size;
    const float* x    = (const float*)d_in[0];
    const float* Wq   = (const float*)d_in[1];
    const float* bq   = (const float*)d_in[2];
    const float* Wkv  = (const float*)d_in[3];
    const float* bkv  = (const float*)d_in[4];
    const float* Wo   = (const float*)d_in[5];
    const float* bo   = (const float*)d_in[6];
    const float* rmsw = (const float*)d_in[7];
    const float* l1   = (const float*)d_in[8];
    const float* l2   = (const float*)d_in[9];
    const float* l3   = (const float*)d_in[10];
    const float* inw  = (const float*)d_in[11];
    const float* inb  = (const float*)d_in[12];
    float* out = (float*)d_out;

    float *q, *kv, *o, *att, *hbuf, *gate, *ffn, *ps, *pq, *mn, *rs, *sc, *sv;
    cudaGetSymbolAddress((void**)&q,    g_q);
    cudaGetSymbolAddress((void**)&kv,   g_kv);
    cudaGetSymbolAddress((void**)&o,    g_o);
    cudaGetSymbolAddress((void**)&att,  g_att);
    cudaGetSymbolAddress((void**)&hbuf, g_h);
    cudaGetSymbolAddress((void**)&gate, g_gate);
    cudaGetSymbolAddress((void**)&ffn,  g_ffn);
    cudaGetSymbolAddress((void**)&ps,   g_psum);
    cudaGetSymbolAddress((void**)&pq,   g_psq);
    cudaGetSymbolAddress((void**)&mn,   g_mean);
    cudaGetSymbolAddress((void**)&rs,   g_rstd);
    cudaGetSymbolAddress((void**)&sc,   g_sc);
    cudaGetSymbolAddress((void**)&sv,   g_sinv);

    const int gemmSmem = (2*A_BUF_F32 + 2*B_BUF_F32) * 4;   // 67584 B
    cudaFuncSetAttribute(tf32gemm_kernel,   cudaFuncAttributeMaxDynamicSharedMemorySize, gemmSmem);
    cudaFuncSetAttribute(qkv_gemm_kernel,   cudaFuncAttributeMaxDynamicSharedMemorySize, gemmSmem);
    cudaFuncSetAttribute(ffn12_gemm_kernel, cudaFuncAttributeMaxDynamicSharedMemorySize, gemmSmem);
    const int scoresSmem = 2*128*SST*4;                      // 69632 B
    cudaFuncSetAttribute(scores_kernel, cudaFuncAttributeMaxDynamicSharedMemorySize, scoresSmem);
    const int avSmem = (2*64*AWST + 2*64*AVST) * 4;          // 71680 B
    cudaFuncSetAttribute(av_kernel, cudaFuncAttributeMaxDynamicSharedMemorySize, avSmem);

    // fused QKV projection (virtual N = 1536 -> 384 blocks); writes tf32-rounded q/kv
    qkv_gemm_kernel<<<dim3(3*DMODEL/128, MTOT/128), 256, gemmSmem>>>(x, Wq, bq, Wkv, bkv, q, kv);

    // sparse attention: scores -> select -> AV
    scores_kernel<<<dim3(SEQ/128, SEQ/128, BSZ*NH), 256, scoresSmem>>>(q, kv, sc);
    select_kernel<<<BSZ*NH*SEQ/8, 256>>>(sc, sv);
    av_kernel<<<dim3(SEQ/64, BSZ*NH), 256, avSmem>>>(sc, kv, sv, o);

    // output projection + residual + rmsnorm
    tf32gemm_kernel<<<dim3(DMODEL/128, MTOT/128), 256, gemmSmem>>>(o, Wo, bo, att, MTOT, DMODEL, DMODEL);
    rms_add_kernel<<<MTOT, 128>>>(x, att, rmsw, hbuf);

    // SwiGLU FFN: gate = silu(h@l1) * (h@l2) in ONE launch; then l3
    ffn12_gemm_kernel<<<dim3(INNER_DIM/64, MTOT/128), 256, gemmSmem>>>(hbuf, l1, l2, gate);
    tf32gemm_kernel<<<dim3(DMODEL/128, MTOT/128), 256, gemmSmem>>>(gate, l3, nullptr, ffn, MTOT, DMODEL, INNER_DIM);

    // instance norm over sequence
    in1_kernel<<<dim3(32, BSZ), 256>>>(hbuf, ffn, ps, pq);
    in2_kernel<<<BSZ, DMODEL>>>(ps, pq, mn, rs);
    in3_kernel<<<(MTOT*DMODEL + 255)/256, 256>>>(hbuf, ffn, mn, rs, inw, inb, out);
}